// round 3
// baseline (speedup 1.0000x reference)
#include <cuda_runtime.h>
#include <math.h>

#define NN  384
#define DIM 512
#define NH  8
#define NF  64

typedef unsigned long long ull;

// ---------------- packed f32x2 helpers ----------------
__device__ __forceinline__ ull bcast2(float s) {
    ull r; asm("mov.b64 %0, {%1, %1};" : "=l"(r) : "f"(s)); return r;
}
__device__ __forceinline__ void unpack2(ull v, float& lo, float& hi) {
    asm("mov.b64 {%0, %1}, %2;" : "=f"(lo), "=f"(hi) : "l"(v));
}
__device__ __forceinline__ ull fma2(ull a, ull b, ull c) {
    ull d; asm("fma.rn.f32x2 %0, %1, %2, %3;" : "=l"(d) : "l"(a), "l"(b), "l"(c));
    return d;
}
__device__ __forceinline__ ull add2(ull a, ull b) {
    ull d; asm("add.rn.f32x2 %0, %1, %2;" : "=l"(d) : "l"(a), "l"(b));
    return d;
}
__device__ __forceinline__ ull abs2(ull v) { return v & 0x7FFFFFFF7FFFFFFFULL; }

// ---------------- scratch (device globals) ----------------
__device__ float g_glT[NH * NF * NN];  // transposed g_l: [h][f][j]  (j contiguous)
__device__ float g_gr[NN * DIM];
__device__ float g_c[2 * NH * NN];     // [which(l=0,r=1)][h][n]
__device__ float g_x1[NN * DIM];       // layer-0 output / layer-1 input

// =================== GEMM + fused c-vector + transpose epilogue ============
// O[384,512] = X @ W.  z=0 -> writes g_glT (transposed) ; z=1 -> writes g_gr.
// Both write c[n] = sum_f a[f]*O[n, h*64+f].
#define BM 16
#define BN 64
#define BK 32

__global__ void __launch_bounds__(128)
gemm_kernel(const float* __restrict__ Xp,
            const float* __restrict__ Wl,
            const float* __restrict__ Wr,
            const float* __restrict__ av,
            int use_x1) {
    const float* X = use_x1 ? g_x1 : Xp;
    const float* W = blockIdx.z ? Wr : Wl;
    int h  = blockIdx.x;
    int m0 = blockIdx.y * BM;
    int n0 = h * BN;
    float* cvec = g_c + blockIdx.z * (NH * NN) + h * NN;

    __shared__ float2 As2[BK][BM + 4];    // duplicated (v,v) pairs, row=k (stride 160B)
    __shared__ float  Bs[BK][BN + 16];    // stride 320B: conflict-free + 16B aligned

    int tid = threadIdx.x;
    int tx = tid & 15, ty = tid >> 4;

    int mX  = tid >> 3, kqX = (tid & 7) * 4;   // X loader
    int kW  = tid >> 2, ncW = (tid & 3) * 4;   // W loader: 4 float4 at +0,+16,+32,+48

    const float* xptr = X + (m0 + mX) * DIM + kqX;
    const float* wptr = W + kW * DIM + n0 + ncW;

    float4 xb  = *(const float4*)xptr;
    float4 wb0 = *(const float4*)(wptr);
    float4 wb1 = *(const float4*)(wptr + 16);
    float4 wb2 = *(const float4*)(wptr + 32);
    float4 wb3 = *(const float4*)(wptr + 48);

    ull acc00 = 0, acc01 = 0, acc10 = 0, acc11 = 0;

    const int NT = DIM / BK;     // 16
    for (int t = 0; t < NT; t++) {
        As2[kqX + 0][mX] = make_float2(xb.x, xb.x);
        As2[kqX + 1][mX] = make_float2(xb.y, xb.y);
        As2[kqX + 2][mX] = make_float2(xb.z, xb.z);
        As2[kqX + 3][mX] = make_float2(xb.w, xb.w);
        *(float4*)&Bs[kW][ncW]      = wb0;
        *(float4*)&Bs[kW][ncW + 16] = wb1;
        *(float4*)&Bs[kW][ncW + 32] = wb2;
        *(float4*)&Bs[kW][ncW + 48] = wb3;
        __syncthreads();

        if (t + 1 < NT) {   // register prefetch of next tile
            xb  = *(const float4*)(xptr + (t + 1) * BK);
            const float* wn = wptr + (t + 1) * BK * DIM;
            wb0 = *(const float4*)(wn);
            wb1 = *(const float4*)(wn + 16);
            wb2 = *(const float4*)(wn + 32);
            wb3 = *(const float4*)(wn + 48);
        }

#pragma unroll
        for (int k = 0; k < BK; k++) {
            ulonglong2 pa = *(const ulonglong2*)&As2[k][ty * 2];
            ulonglong2 pb = *(const ulonglong2*)&Bs[k][tx * 4];
            acc00 = fma2(pa.x, pb.x, acc00);
            acc01 = fma2(pa.x, pb.y, acc01);
            acc10 = fma2(pa.y, pb.x, acc10);
            acc11 = fma2(pa.y, pb.y, acc11);
        }
        __syncthreads();
    }

    float v00, v01, v02, v03, v10, v11, v12, v13;
    unpack2(acc00, v00, v01); unpack2(acc01, v02, v03);
    unpack2(acc10, v10, v11); unpack2(acc11, v12, v13);

    int row0 = m0 + ty * 2;
    if (blockIdx.z) {     // g_r: row-major
        *(float4*)&g_gr[row0 * DIM + n0 + tx * 4]       = make_float4(v00, v01, v02, v03);
        *(float4*)&g_gr[(row0 + 1) * DIM + n0 + tx * 4] = make_float4(v10, v11, v12, v13);
    } else {              // g_l: transposed [h][f][j]
        float* gt = g_glT + (n0 + tx * 4) * NN + row0;
        *(float2*)(gt + 0 * NN) = make_float2(v00, v10);
        *(float2*)(gt + 1 * NN) = make_float2(v01, v11);
        *(float2*)(gt + 2 * NN) = make_float2(v02, v12);
        *(float2*)(gt + 3 * NN) = make_float2(v03, v13);
    }

    float4 af = *(const float4*)&av[tx * 4];
    float cp0 = fmaf(af.x, v00, fmaf(af.y, v01, fmaf(af.z, v02, af.w * v03)));
    float cp1 = fmaf(af.x, v10, fmaf(af.y, v11, fmaf(af.z, v12, af.w * v13)));
#pragma unroll
    for (int o = 8; o; o >>= 1) {
        cp0 += __shfl_xor_sync(0xffffffffu, cp0, o);
        cp1 += __shfl_xor_sync(0xffffffffu, cp1, o);
    }
    if (tx == 0) {
        cvec[row0]     = cp0;
        cvec[row0 + 1] = cp1;
    }
}

// =================== fused attention (2 barriers total) =====================
#define TI 8

__global__ void __launch_bounds__(128)
attn_kernel(const float* __restrict__ a,
            const int* __restrict__ adj,
            const float* __restrict__ x_in_p,
            float* __restrict__ x_out_p,
            int mode) {                    // 0: layer0 (ELU), 1: layer1
    __shared__ float att_s[TI][NN];        // 12288 B
    __shared__ float red[4][TI][NF];       //  8192 B

    const float* x_in = mode ? g_x1 : x_in_p;
    float* x_out      = mode ? x_out_p : g_x1;

    int h  = blockIdx.y;
    int i0 = blockIdx.x * TI;
    int tid = threadIdx.x, lane = tid & 31, w = tid >> 5;
    int jbase = 2 * lane;

    // ---- phase 1: acc[i][jpair] += 0.4a[f] * |g_r[i,f] + g_l[j,f]| ----
    // g_l read transposed from global (coalesced, L1/L2-hot). No smem, no barriers.
    ull acc2[2][6];
#pragma unroll
    for (int il = 0; il < 2; il++)
#pragma unroll
        for (int jt = 0; jt < 6; jt++) acc2[il][jt] = 0ULL;

    const float* glT = g_glT + h * (NF * NN);
    const float* gr0 = g_gr + (i0 + w * 2) * DIM + h * NF;
    const float* gr1 = gr0 + DIM;

#pragma unroll 1
    for (int fc = 0; fc < 16; fc++) {
        float4 ga  = *(const float4*)(gr0 + fc * 4);
        float4 gb  = *(const float4*)(gr1 + fc * 4);
        float4 av4 = *(const float4*)(a + fc * 4);
        ull pa[4], pg0[4], pg1[4];
        pa[0] = bcast2(0.4f * av4.x); pa[1] = bcast2(0.4f * av4.y);
        pa[2] = bcast2(0.4f * av4.z); pa[3] = bcast2(0.4f * av4.w);
        pg0[0] = bcast2(ga.x); pg0[1] = bcast2(ga.y);
        pg0[2] = bcast2(ga.z); pg0[3] = bcast2(ga.w);
        pg1[0] = bcast2(gb.x); pg1[1] = bcast2(gb.y);
        pg1[2] = bcast2(gb.z); pg1[3] = bcast2(gb.w);
#pragma unroll
        for (int f4 = 0; f4 < 4; f4++) {
            const float* gp = glT + (fc * 4 + f4) * NN + jbase;
#pragma unroll
            for (int jt = 0; jt < 6; jt++) {
                ull gl2 = *(const ull*)(gp + jt * 64);
                acc2[0][jt] = fma2(pa[f4], abs2(add2(pg0[f4], gl2)), acc2[0][jt]);
                acc2[1][jt] = fma2(pa[f4], abs2(add2(pg1[f4], gl2)), acc2[1][jt]);
            }
        }
    }

    // ---- masked softmax over j (per warp, two rows); write att_s[i][j] ----
    const float* clv = g_c + h * NN;
    const float* crv = g_c + NH * NN + h * NN;
#pragma unroll
    for (int il = 0; il < 2; il++) {
        int i = i0 + w * 2 + il;
        float cr6 = 0.6f * crv[i];
        float e[12];
        unsigned vm = 0;
        float m = -1e30f;
#pragma unroll
        for (int jt = 0; jt < 6; jt++) {
            int j0 = jt * 64 + jbase;
            float2 gcl = *(const float2*)(clv + j0);
            int2   adv = *(const int2*)(adj + i * NN + j0);
            float u0, u1; unpack2(acc2[il][jt], u0, u1);
            float e0 = cr6 + fmaf(0.6f, gcl.x, u0);
            float e1 = cr6 + fmaf(0.6f, gcl.y, u1);
            e[jt * 2] = e0; e[jt * 2 + 1] = e1;
            if (adv.x || (j0 == i))     { vm |= 1u << (jt * 2);     m = fmaxf(m, e0); }
            if (adv.y || (j0 + 1 == i)) { vm |= 1u << (jt * 2 + 1); m = fmaxf(m, e1); }
        }
#pragma unroll
        for (int o = 16; o; o >>= 1) m = fmaxf(m, __shfl_xor_sync(0xffffffffu, m, o));
        float sum = 0.f;
#pragma unroll
        for (int q = 0; q < 12; q++) {
            float p = ((vm >> q) & 1) ? __expf(e[q] - m) : 0.f;
            e[q] = p; sum += p;
        }
#pragma unroll
        for (int o = 16; o; o >>= 1) sum += __shfl_xor_sync(0xffffffffu, sum, o);
        float inv = 1.f / sum;
#pragma unroll
        for (int jt = 0; jt < 6; jt++)
            *(float2*)&att_s[w * 2 + il][jt * 64 + jbase] =
                make_float2(e[jt * 2] * inv, e[jt * 2 + 1] * inv);
    }
    __syncthreads();   // barrier #1

    // ---- phase 2: j-partitioned, barrier-free streaming ----
    // warp w owns j in [w*96, (w+1)*96); accumulates all 8 i-rows for its f-pair.
    ull o[TI];
#pragma unroll
    for (int q = 0; q < TI; q++) o[q] = 0ULL;

    const float* grp = g_gr + h * NF + jbase;
#pragma unroll 4
    for (int jj = 0; jj < 96; jj++) {
        int j = w * 96 + jj;
        ull gp = *(const ull*)(grp + j * DIM);
#pragma unroll
        for (int q = 0; q < TI; q++)
            o[q] = fma2(bcast2(att_s[q][j]), gp, o[q]);
    }
#pragma unroll
    for (int q = 0; q < TI; q++)
        *(ull*)&red[w][q][jbase] = o[q];
    __syncthreads();   // barrier #2

    // ---- reduce partials + activation + residual ----
    {
        int i = tid >> 4, f4 = (tid & 15) * 4;
        float4 s0 = *(const float4*)&red[0][i][f4];
        float4 s1 = *(const float4*)&red[1][i][f4];
        float4 s2 = *(const float4*)&red[2][i][f4];
        float4 s3 = *(const float4*)&red[3][i][f4];
        float r0 = s0.x + s1.x + s2.x + s3.x;
        float r1 = s0.y + s1.y + s2.y + s3.y;
        float r2 = s0.z + s1.z + s2.z + s3.z;
        float r3 = s0.w + s1.w + s2.w + s3.w;
        if (mode == 0) {       // ELU (alpha=1)
            r0 = r0 > 0.f ? r0 : expm1f(r0);
            r1 = r1 > 0.f ? r1 : expm1f(r1);
            r2 = r2 > 0.f ? r2 : expm1f(r2);
            r3 = r3 > 0.f ? r3 : expm1f(r3);
        }
        int gi = i0 + i;
        const float* xp = x_in + gi * DIM + h * NF + f4;
        float4 xi = *(const float4*)xp;
        *(float4*)&x_out[gi * DIM + h * NF + f4] =
            make_float4(xi.x + r0, xi.y + r1, xi.z + r2, xi.w + r3);
    }
}

// ---------------------------------------------------------------------------
extern "C" void kernel_launch(void* const* d_in, const int* in_sizes, int n_in,
                              void* d_out, int out_size) {
    const float* x   = (const float*)d_in[0];
    const int*   adj = (const int*)  d_in[1];
    const float* Wl0 = (const float*)d_in[2];
    const float* Wr0 = (const float*)d_in[3];
    const float* a0  = (const float*)d_in[4];
    const float* Wl1 = (const float*)d_in[5];
    const float* Wr1 = (const float*)d_in[6];
    const float* a1  = (const float*)d_in[7];
    float* out = (float*)d_out;

    dim3 gg(NH, NN / BM, 2);      // (8, 24, 2) = 384 blocks
    dim3 ga(NN / TI, NH);         // (48, 8)    = 384 blocks

    // layer 0
    gemm_kernel<<<gg, 128>>>(x, Wl0, Wr0, a0, 0);
    attn_kernel<<<ga, 128>>>(a0, adj, x, out, 0);    // -> g_x1 (ELU + residual)
    // layer 1
    gemm_kernel<<<gg, 128>>>(x, Wl1, Wr1, a1, 1);
    attn_kernel<<<ga, 128>>>(a1, adj, x, out, 1);    // -> d_out (residual)
}

// round 4
// speedup vs baseline: 1.0251x; 1.0251x over previous
#include <cuda_runtime.h>
#include <math.h>

#define NN  384
#define DIM 512
#define NH  8
#define NF  64

typedef unsigned long long ull;

// ---------------- packed f32x2 helpers ----------------
__device__ __forceinline__ ull bcast2(float s) {
    ull r; asm("mov.b64 %0, {%1, %1};" : "=l"(r) : "f"(s)); return r;
}
__device__ __forceinline__ void unpack2(ull v, float& lo, float& hi) {
    asm("mov.b64 {%0, %1}, %2;" : "=f"(lo), "=f"(hi) : "l"(v));
}
__device__ __forceinline__ ull fma2(ull a, ull b, ull c) {
    ull d; asm("fma.rn.f32x2 %0, %1, %2, %3;" : "=l"(d) : "l"(a), "l"(b), "l"(c));
    return d;
}
__device__ __forceinline__ ull add2(ull a, ull b) {
    ull d; asm("add.rn.f32x2 %0, %1, %2;" : "=l"(d) : "l"(a), "l"(b));
    return d;
}
__device__ __forceinline__ ull abs2(ull v) { return v & 0x7FFFFFFF7FFFFFFFULL; }

// ---------------- scratch (device globals) ----------------
__device__ float g_glT[NH * NF * NN];  // transposed g_l: [h][f][j]  (j contiguous)
__device__ float g_gr[NN * DIM];
__device__ float g_c[2 * NH * NN];     // [which(l=0,r=1)][h][n]
__device__ float g_x1[NN * DIM];       // layer-0 output / layer-1 input

// =================== GEMM + fused c-vector + transpose epilogue ============
// O[384,512] = X @ W.  z=0 -> writes g_glT (transposed) ; z=1 -> writes g_gr.
// Both write c[n] = sum_f a[f]*O[n, h*64+f].
#define BM 16
#define BN 64
#define BK 32

__global__ void __launch_bounds__(128)
gemm_kernel(const float* __restrict__ Xp,
            const float* __restrict__ Wl,
            const float* __restrict__ Wr,
            const float* __restrict__ av,
            int use_x1) {
    const float* X = use_x1 ? g_x1 : Xp;
    const float* W = blockIdx.z ? Wr : Wl;
    int h  = blockIdx.x;
    int m0 = blockIdx.y * BM;
    int n0 = h * BN;
    float* cvec = g_c + blockIdx.z * (NH * NN) + h * NN;

    __shared__ float2 As2[BK][BM + 4];    // duplicated (v,v) pairs, row=k (stride 160B)
    __shared__ float  Bs[BK][BN + 16];    // stride 320B: conflict-free + 16B aligned

    int tid = threadIdx.x;
    int tx = tid & 15, ty = tid >> 4;

    int mX  = tid >> 3, kqX = (tid & 7) * 4;   // X loader
    int kW  = tid >> 2, ncW = (tid & 3) * 4;   // W loader: 4 float4 at +0,+16,+32,+48

    const float* xptr = X + (m0 + mX) * DIM + kqX;
    const float* wptr = W + kW * DIM + n0 + ncW;

    float4 xb  = *(const float4*)xptr;
    float4 wb0 = *(const float4*)(wptr);
    float4 wb1 = *(const float4*)(wptr + 16);
    float4 wb2 = *(const float4*)(wptr + 32);
    float4 wb3 = *(const float4*)(wptr + 48);

    ull acc00 = 0, acc01 = 0, acc10 = 0, acc11 = 0;

    const int NT = DIM / BK;     // 16
    for (int t = 0; t < NT; t++) {
        As2[kqX + 0][mX] = make_float2(xb.x, xb.x);
        As2[kqX + 1][mX] = make_float2(xb.y, xb.y);
        As2[kqX + 2][mX] = make_float2(xb.z, xb.z);
        As2[kqX + 3][mX] = make_float2(xb.w, xb.w);
        *(float4*)&Bs[kW][ncW]      = wb0;
        *(float4*)&Bs[kW][ncW + 16] = wb1;
        *(float4*)&Bs[kW][ncW + 32] = wb2;
        *(float4*)&Bs[kW][ncW + 48] = wb3;
        __syncthreads();

        if (t + 1 < NT) {   // register prefetch of next tile
            xb  = *(const float4*)(xptr + (t + 1) * BK);
            const float* wn = wptr + (t + 1) * BK * DIM;
            wb0 = *(const float4*)(wn);
            wb1 = *(const float4*)(wn + 16);
            wb2 = *(const float4*)(wn + 32);
            wb3 = *(const float4*)(wn + 48);
        }

#pragma unroll
        for (int k = 0; k < BK; k++) {
            ulonglong2 pa = *(const ulonglong2*)&As2[k][ty * 2];
            ulonglong2 pb = *(const ulonglong2*)&Bs[k][tx * 4];
            acc00 = fma2(pa.x, pb.x, acc00);
            acc01 = fma2(pa.x, pb.y, acc01);
            acc10 = fma2(pa.y, pb.x, acc10);
            acc11 = fma2(pa.y, pb.y, acc11);
        }
        __syncthreads();
    }

    float v00, v01, v02, v03, v10, v11, v12, v13;
    unpack2(acc00, v00, v01); unpack2(acc01, v02, v03);
    unpack2(acc10, v10, v11); unpack2(acc11, v12, v13);

    int row0 = m0 + ty * 2;
    if (blockIdx.z) {     // g_r: row-major
        *(float4*)&g_gr[row0 * DIM + n0 + tx * 4]       = make_float4(v00, v01, v02, v03);
        *(float4*)&g_gr[(row0 + 1) * DIM + n0 + tx * 4] = make_float4(v10, v11, v12, v13);
    } else {              // g_l: transposed [h][f][j]
        float* gt = g_glT + (n0 + tx * 4) * NN + row0;
        *(float2*)(gt + 0 * NN) = make_float2(v00, v10);
        *(float2*)(gt + 1 * NN) = make_float2(v01, v11);
        *(float2*)(gt + 2 * NN) = make_float2(v02, v12);
        *(float2*)(gt + 3 * NN) = make_float2(v03, v13);
    }

    float4 af = *(const float4*)&av[tx * 4];
    float cp0 = fmaf(af.x, v00, fmaf(af.y, v01, fmaf(af.z, v02, af.w * v03)));
    float cp1 = fmaf(af.x, v10, fmaf(af.y, v11, fmaf(af.z, v12, af.w * v13)));
#pragma unroll
    for (int o = 8; o; o >>= 1) {
        cp0 += __shfl_xor_sync(0xffffffffu, cp0, o);
        cp1 += __shfl_xor_sync(0xffffffffu, cp1, o);
    }
    if (tx == 0) {
        cvec[row0]     = cp0;
        cvec[row0 + 1] = cp1;
    }
}

// =================== fused attention (2 barriers total) =====================
#define TI 8

__global__ void __launch_bounds__(128)
attn_kernel(const float* __restrict__ a,
            const int* __restrict__ adj,
            const float* __restrict__ x_in_p,
            float* __restrict__ x_out_p,
            int mode) {                    // 0: layer0 (ELU), 1: layer1
    __shared__ float att_s[TI][NN];        // 12288 B
    __shared__ float red[4][TI][NF];       //  8192 B

    const float* x_in = mode ? g_x1 : x_in_p;
    float* x_out      = mode ? x_out_p : g_x1;

    int h  = blockIdx.y;
    int i0 = blockIdx.x * TI;
    int tid = threadIdx.x, lane = tid & 31, w = tid >> 5;
    int jbase = 2 * lane;

    // ---- phase 1: acc[i][jpair] += 0.4a[f] * |g_r[i,f] + g_l[j,f]| ----
    // g_l read transposed from global (coalesced, L1/L2-hot). No smem, no barriers.
    ull acc2[2][6];
#pragma unroll
    for (int il = 0; il < 2; il++)
#pragma unroll
        for (int jt = 0; jt < 6; jt++) acc2[il][jt] = 0ULL;

    const float* glT = g_glT + h * (NF * NN);
    const float* gr0 = g_gr + (i0 + w * 2) * DIM + h * NF;
    const float* gr1 = gr0 + DIM;

#pragma unroll 1
    for (int fc = 0; fc < 16; fc++) {
        float4 ga  = *(const float4*)(gr0 + fc * 4);
        float4 gb  = *(const float4*)(gr1 + fc * 4);
        float4 av4 = *(const float4*)(a + fc * 4);
        ull pa[4], pg0[4], pg1[4];
        pa[0] = bcast2(0.4f * av4.x); pa[1] = bcast2(0.4f * av4.y);
        pa[2] = bcast2(0.4f * av4.z); pa[3] = bcast2(0.4f * av4.w);
        pg0[0] = bcast2(ga.x); pg0[1] = bcast2(ga.y);
        pg0[2] = bcast2(ga.z); pg0[3] = bcast2(ga.w);
        pg1[0] = bcast2(gb.x); pg1[1] = bcast2(gb.y);
        pg1[2] = bcast2(gb.z); pg1[3] = bcast2(gb.w);
#pragma unroll
        for (int f4 = 0; f4 < 4; f4++) {
            const float* gp = glT + (fc * 4 + f4) * NN + jbase;
#pragma unroll
            for (int jt = 0; jt < 6; jt++) {
                ull gl2 = *(const ull*)(gp + jt * 64);
                acc2[0][jt] = fma2(pa[f4], abs2(add2(pg0[f4], gl2)), acc2[0][jt]);
                acc2[1][jt] = fma2(pa[f4], abs2(add2(pg1[f4], gl2)), acc2[1][jt]);
            }
        }
    }

    // ---- masked softmax over j (per warp, two rows); write att_s[i][j] ----
    const float* clv = g_c + h * NN;
    const float* crv = g_c + NH * NN + h * NN;
#pragma unroll
    for (int il = 0; il < 2; il++) {
        int i = i0 + w * 2 + il;
        float cr6 = 0.6f * crv[i];
        float e[12];
        unsigned vm = 0;
        float m = -1e30f;
#pragma unroll
        for (int jt = 0; jt < 6; jt++) {
            int j0 = jt * 64 + jbase;
            float2 gcl = *(const float2*)(clv + j0);
            int2   adv = *(const int2*)(adj + i * NN + j0);
            float u0, u1; unpack2(acc2[il][jt], u0, u1);
            float e0 = cr6 + fmaf(0.6f, gcl.x, u0);
            float e1 = cr6 + fmaf(0.6f, gcl.y, u1);
            e[jt * 2] = e0; e[jt * 2 + 1] = e1;
            if (adv.x || (j0 == i))     { vm |= 1u << (jt * 2);     m = fmaxf(m, e0); }
            if (adv.y || (j0 + 1 == i)) { vm |= 1u << (jt * 2 + 1); m = fmaxf(m, e1); }
        }
#pragma unroll
        for (int o = 16; o; o >>= 1) m = fmaxf(m, __shfl_xor_sync(0xffffffffu, m, o));
        float sum = 0.f;
#pragma unroll
        for (int q = 0; q < 12; q++) {
            float p = ((vm >> q) & 1) ? __expf(e[q] - m) : 0.f;
            e[q] = p; sum += p;
        }
#pragma unroll
        for (int o = 16; o; o >>= 1) sum += __shfl_xor_sync(0xffffffffu, sum, o);
        float inv = 1.f / sum;
#pragma unroll
        for (int jt = 0; jt < 6; jt++)
            *(float2*)&att_s[w * 2 + il][jt * 64 + jbase] =
                make_float2(e[jt * 2] * inv, e[jt * 2 + 1] * inv);
    }
    __syncthreads();   // barrier #1

    // ---- phase 2: j-partitioned, barrier-free streaming ----
    // warp w owns j in [w*96, (w+1)*96); accumulates all 8 i-rows for its f-pair.
    ull o[TI];
#pragma unroll
    for (int q = 0; q < TI; q++) o[q] = 0ULL;

    const float* grp = g_gr + h * NF + jbase;
#pragma unroll 4
    for (int jj = 0; jj < 96; jj++) {
        int j = w * 96 + jj;
        ull gp = *(const ull*)(grp + j * DIM);
#pragma unroll
        for (int q = 0; q < TI; q++)
            o[q] = fma2(bcast2(att_s[q][j]), gp, o[q]);
    }
#pragma unroll
    for (int q = 0; q < TI; q++)
        *(ull*)&red[w][q][jbase] = o[q];
    __syncthreads();   // barrier #2

    // ---- reduce partials + activation + residual ----
    {
        int i = tid >> 4, f4 = (tid & 15) * 4;
        float4 s0 = *(const float4*)&red[0][i][f4];
        float4 s1 = *(const float4*)&red[1][i][f4];
        float4 s2 = *(const float4*)&red[2][i][f4];
        float4 s3 = *(const float4*)&red[3][i][f4];
        float r0 = s0.x + s1.x + s2.x + s3.x;
        float r1 = s0.y + s1.y + s2.y + s3.y;
        float r2 = s0.z + s1.z + s2.z + s3.z;
        float r3 = s0.w + s1.w + s2.w + s3.w;
        if (mode == 0) {       // ELU (alpha=1)
            r0 = r0 > 0.f ? r0 : expm1f(r0);
            r1 = r1 > 0.f ? r1 : expm1f(r1);
            r2 = r2 > 0.f ? r2 : expm1f(r2);
            r3 = r3 > 0.f ? r3 : expm1f(r3);
        }
        int gi = i0 + i;
        const float* xp = x_in + gi * DIM + h * NF + f4;
        float4 xi = *(const float4*)xp;
        *(float4*)&x_out[gi * DIM + h * NF + f4] =
            make_float4(xi.x + r0, xi.y + r1, xi.z + r2, xi.w + r3);
    }
}

// ---------------------------------------------------------------------------
extern "C" void kernel_launch(void* const* d_in, const int* in_sizes, int n_in,
                              void* d_out, int out_size) {
    const float* x   = (const float*)d_in[0];
    const int*   adj = (const int*)  d_in[1];
    const float* Wl0 = (const float*)d_in[2];
    const float* Wr0 = (const float*)d_in[3];
    const float* a0  = (const float*)d_in[4];
    const float* Wl1 = (const float*)d_in[5];
    const float* Wr1 = (const float*)d_in[6];
    const float* a1  = (const float*)d_in[7];
    float* out = (float*)d_out;

    dim3 gg(NH, NN / BM, 2);      // (8, 24, 2) = 384 blocks
    dim3 ga(NN / TI, NH);         // (48, 8)    = 384 blocks

    // layer 0
    gemm_kernel<<<gg, 128>>>(x, Wl0, Wr0, a0, 0);
    attn_kernel<<<ga, 128>>>(a0, adj, x, out, 0);    // -> g_x1 (ELU + residual)
    // layer 1
    gemm_kernel<<<gg, 128>>>(x, Wl1, Wr1, a1, 1);
    attn_kernel<<<ga, 128>>>(a1, adj, x, out, 1);    // -> d_out (residual)
}

// round 5
// speedup vs baseline: 1.2624x; 1.2314x over previous
#include <cuda_runtime.h>
#include <math.h>

#define NN  384
#define DIM 512
#define NH  8
#define NF  64

typedef unsigned long long ull;

// ---------------- packed f32x2 helpers ----------------
__device__ __forceinline__ void unpack2(ull v, float& lo, float& hi) {
    asm("mov.b64 {%0, %1}, %2;" : "=f"(lo), "=f"(hi) : "l"(v));
}
__device__ __forceinline__ ull fma2(ull a, ull b, ull c) {
    ull d; asm("fma.rn.f32x2 %0, %1, %2, %3;" : "=l"(d) : "l"(a), "l"(b), "l"(c));
    return d;
}
__device__ __forceinline__ ull add2(ull a, ull b) {
    ull d; asm("add.rn.f32x2 %0, %1, %2;" : "=l"(d) : "l"(a), "l"(b));
    return d;
}
__device__ __forceinline__ ull abs2(ull v) { return v & 0x7FFFFFFF7FFFFFFFULL; }

// ---------------- scratch (device globals) ----------------
__device__ float g_glT[NH * NF * NN];  // transposed g_l: [h][f][j]
__device__ float g_gr[NN * DIM];
__device__ float g_c[2 * NH * NN];     // [which(l=0,r=1)][h][n]
__device__ float g_x1[NN * DIM];       // layer-0 output / layer-1 input

// =================== GEMM (double-buffered) + fused epilogues ===============
#define BM 16
#define BN 64
#define BK 32

__global__ void __launch_bounds__(128)
gemm_kernel(const float* __restrict__ Xp,
            const float* __restrict__ Wl,
            const float* __restrict__ Wr,
            const float* __restrict__ av,
            int use_x1) {
    const float* X = use_x1 ? g_x1 : Xp;
    const float* W = blockIdx.z ? Wr : Wl;
    int h  = blockIdx.x;
    int m0 = blockIdx.y * BM;
    int n0 = h * BN;
    float* cvec = g_c + blockIdx.z * (NH * NN) + h * NN;

    __shared__ float2 As2[2][BK][BM + 4];   // (v,v) pairs, row=k
    __shared__ float  Bs[2][BK][BN + 16];

    int tid = threadIdx.x;
    int tx = tid & 15, ty = tid >> 4;

    int mX  = tid >> 3, kqX = (tid & 7) * 4;
    int kW  = tid >> 2, ncW = (tid & 3) * 4;

    const float* xptr = X + (m0 + mX) * DIM + kqX;
    const float* wptr = W + kW * DIM + n0 + ncW;

    float4 xb  = *(const float4*)xptr;
    float4 wb0 = *(const float4*)(wptr);
    float4 wb1 = *(const float4*)(wptr + 16);
    float4 wb2 = *(const float4*)(wptr + 32);
    float4 wb3 = *(const float4*)(wptr + 48);

    // stage tile 0 into buffer 0
    As2[0][kqX + 0][mX] = make_float2(xb.x, xb.x);
    As2[0][kqX + 1][mX] = make_float2(xb.y, xb.y);
    As2[0][kqX + 2][mX] = make_float2(xb.z, xb.z);
    As2[0][kqX + 3][mX] = make_float2(xb.w, xb.w);
    *(float4*)&Bs[0][kW][ncW]      = wb0;
    *(float4*)&Bs[0][kW][ncW + 16] = wb1;
    *(float4*)&Bs[0][kW][ncW + 32] = wb2;
    *(float4*)&Bs[0][kW][ncW + 48] = wb3;

    ull acc00 = 0, acc01 = 0, acc10 = 0, acc11 = 0;

    const int NT = DIM / BK;     // 16
    int buf = 0;
    for (int t = 0; t < NT; t++) {
        __syncthreads();
        if (t + 1 < NT) {   // prefetch next tile to regs
            xb  = *(const float4*)(xptr + (t + 1) * BK);
            const float* wn = wptr + (t + 1) * BK * DIM;
            wb0 = *(const float4*)(wn);
            wb1 = *(const float4*)(wn + 16);
            wb2 = *(const float4*)(wn + 32);
            wb3 = *(const float4*)(wn + 48);
        }
#pragma unroll
        for (int k = 0; k < BK; k++) {
            ulonglong2 pa = *(const ulonglong2*)&As2[buf][k][ty * 2];
            ulonglong2 pb = *(const ulonglong2*)&Bs[buf][k][tx * 4];
            acc00 = fma2(pa.x, pb.x, acc00);
            acc01 = fma2(pa.x, pb.y, acc01);
            acc10 = fma2(pa.y, pb.x, acc10);
            acc11 = fma2(pa.y, pb.y, acc11);
        }
        if (t + 1 < NT) {   // stage next tile into other buffer
            int nb = buf ^ 1;
            As2[nb][kqX + 0][mX] = make_float2(xb.x, xb.x);
            As2[nb][kqX + 1][mX] = make_float2(xb.y, xb.y);
            As2[nb][kqX + 2][mX] = make_float2(xb.z, xb.z);
            As2[nb][kqX + 3][mX] = make_float2(xb.w, xb.w);
            *(float4*)&Bs[nb][kW][ncW]      = wb0;
            *(float4*)&Bs[nb][kW][ncW + 16] = wb1;
            *(float4*)&Bs[nb][kW][ncW + 32] = wb2;
            *(float4*)&Bs[nb][kW][ncW + 48] = wb3;
        }
        buf ^= 1;
    }

    float v00, v01, v02, v03, v10, v11, v12, v13;
    unpack2(acc00, v00, v01); unpack2(acc01, v02, v03);
    unpack2(acc10, v10, v11); unpack2(acc11, v12, v13);

    int row0 = m0 + ty * 2;
    if (blockIdx.z) {     // g_r: row-major
        *(float4*)&g_gr[row0 * DIM + n0 + tx * 4]       = make_float4(v00, v01, v02, v03);
        *(float4*)&g_gr[(row0 + 1) * DIM + n0 + tx * 4] = make_float4(v10, v11, v12, v13);
    } else {              // g_l: transposed [h][f][j]
        float* gt = g_glT + (n0 + tx * 4) * NN + row0;
        *(float2*)(gt + 0 * NN) = make_float2(v00, v10);
        *(float2*)(gt + 1 * NN) = make_float2(v01, v11);
        *(float2*)(gt + 2 * NN) = make_float2(v02, v12);
        *(float2*)(gt + 3 * NN) = make_float2(v03, v13);
    }

    float4 af = *(const float4*)&av[tx * 4];
    float cp0 = fmaf(af.x, v00, fmaf(af.y, v01, fmaf(af.z, v02, af.w * v03)));
    float cp1 = fmaf(af.x, v10, fmaf(af.y, v11, fmaf(af.z, v12, af.w * v13)));
#pragma unroll
    for (int o = 8; o; o >>= 1) {
        cp0 += __shfl_xor_sync(0xffffffffu, cp0, o);
        cp1 += __shfl_xor_sync(0xffffffffu, cp1, o);
    }
    if (tx == 0) {
        cvec[row0]     = cp0;
        cvec[row0 + 1] = cp1;
    }
}

// =================== fused attention (256 thr, warp = 2 rows x half-j) ======
#define TI 8

__global__ void __launch_bounds__(256)
attn_kernel(const float* __restrict__ a,
            const int* __restrict__ adj,
            const float* __restrict__ x_in_p,
            float* __restrict__ x_out_p,
            int mode) {                       // 0: layer0 (ELU), 1: layer1
    __shared__ float2 att_t[NN][TI];          // duplicated (p,p): 24576 B
    __shared__ float  red[8][TI][NF + 4];     // 17408 B
    __shared__ float2 grdup[TI][NF];          //  4096 B
    __shared__ float2 a4dup[NF];              //   512 B
    __shared__ float2 ms[TI][2];              //   128 B   total ~46.7 KB

    const float* x_in = mode ? g_x1 : x_in_p;
    float* x_out      = mode ? x_out_p : g_x1;

    int h   = blockIdx.y;
    int i0  = blockIdx.x * TI;
    int tid = threadIdx.x, lane = tid & 31, w = tid >> 5;
    int rp  = w >> 1;               // row pair: rows 2rp, 2rp+1
    int jh  = w & 1;                // j half: [jh*192, jh*192+192)

    // ---- stage duplicated operand tables ----
    for (int t = tid; t < TI * NF; t += 256) {
        int r = t >> 6, f = t & 63;
        float v = g_gr[(i0 + r) * DIM + h * NF + f];
        grdup[r][f] = make_float2(v, v);
    }
    if (tid < NF) { float v = 0.4f * a[tid]; a4dup[tid] = make_float2(v, v); }
    __syncthreads();

    // ---- phase 1: acc[i][jpair] += 0.4a[f] * |g_r[i,f] + g_l[j,f]| ----
    ull acc2[2][3];
#pragma unroll
    for (int il = 0; il < 2; il++)
#pragma unroll
        for (int jt = 0; jt < 3; jt++) acc2[il][jt] = 0ULL;

    const float* glT = g_glT + h * (NF * NN) + jh * 192 + 2 * lane;

#pragma unroll 1
    for (int fc = 0; fc < 16; fc++) {
        ull pa[4], pg0[4], pg1[4];
#pragma unroll
        for (int f4 = 0; f4 < 4; f4++) {
            pa[f4]  = *(const ull*)&a4dup[fc * 4 + f4];
            pg0[f4] = *(const ull*)&grdup[rp * 2][fc * 4 + f4];
            pg1[f4] = *(const ull*)&grdup[rp * 2 + 1][fc * 4 + f4];
        }
#pragma unroll
        for (int f4 = 0; f4 < 4; f4++) {
            const float* gp = glT + (fc * 4 + f4) * NN;
#pragma unroll
            for (int jt = 0; jt < 3; jt++) {
                ull gl2 = *(const ull*)(gp + jt * 64);
                acc2[0][jt] = fma2(pa[f4], abs2(add2(pg0[f4], gl2)), acc2[0][jt]);
                acc2[1][jt] = fma2(pa[f4], abs2(add2(pg1[f4], gl2)), acc2[1][jt]);
            }
        }
    }

    // ---- split-j masked softmax: local (m,s), then cross-half combine ----
    const float* clv = g_c + h * NN;
    const float* crv = g_c + NH * NN + h * NN;
    float p[2][6], mh[2];
#pragma unroll
    for (int il = 0; il < 2; il++) {
        int row = rp * 2 + il;
        int i = i0 + row;
        float cr6 = 0.6f * crv[i];
        unsigned vm = 0;
        float m = -1e30f;
#pragma unroll
        for (int jt = 0; jt < 3; jt++) {
            int j0 = jh * 192 + jt * 64 + 2 * lane;
            float2 gcl = *(const float2*)(clv + j0);
            int2   adv = *(const int2*)(adj + i * NN + j0);
            float u0, u1; unpack2(acc2[il][jt], u0, u1);
            float e0 = cr6 + fmaf(0.6f, gcl.x, u0);
            float e1 = cr6 + fmaf(0.6f, gcl.y, u1);
            p[il][jt * 2] = e0; p[il][jt * 2 + 1] = e1;
            if (adv.x || (j0 == i))     { vm |= 1u << (jt * 2);     m = fmaxf(m, e0); }
            if (adv.y || (j0 + 1 == i)) { vm |= 1u << (jt * 2 + 1); m = fmaxf(m, e1); }
        }
#pragma unroll
        for (int o = 16; o; o >>= 1) m = fmaxf(m, __shfl_xor_sync(0xffffffffu, m, o));
        float s = 0.f;
#pragma unroll
        for (int q = 0; q < 6; q++) {
            float pv = ((vm >> q) & 1) ? __expf(p[il][q] - m) : 0.f;
            p[il][q] = pv; s += pv;
        }
#pragma unroll
        for (int o = 16; o; o >>= 1) s += __shfl_xor_sync(0xffffffffu, s, o);
        mh[il] = m;
        if (lane == 0) ms[row][jh] = make_float2(m, s);
    }
    __syncthreads();

#pragma unroll
    for (int il = 0; il < 2; il++) {
        int row = rp * 2 + il;
        float2 v0 = ms[row][0], v1 = ms[row][1];
        float M = fmaxf(v0.x, v1.x);
        float S = v0.y * __expf(v0.x - M) + v1.y * __expf(v1.x - M);
        float scale = __expf(mh[il] - M) / S;
#pragma unroll
        for (int jt = 0; jt < 3; jt++) {
            int j0 = jh * 192 + jt * 64 + 2 * lane;
            float p0 = p[il][jt * 2] * scale;
            float p1 = p[il][jt * 2 + 1] * scale;
            att_t[j0][row]     = make_float2(p0, p0);
            att_t[j0 + 1][row] = make_float2(p1, p1);
        }
    }
    __syncthreads();

    // ---- phase 2: warp owns 48 j, accumulates all 8 rows for its f-pair ----
    ull o[TI];
#pragma unroll
    for (int q = 0; q < TI; q++) o[q] = 0ULL;

    const float* grp = g_gr + h * NF + 2 * lane;
    int jstart = w * 48;
#pragma unroll 4
    for (int jj = 0; jj < 48; jj++) {
        int j = jstart + jj;
        ull gp = *(const ull*)(grp + j * DIM);
#pragma unroll
        for (int q = 0; q < TI; q++)
            o[q] = fma2(*(const ull*)&att_t[j][q], gp, o[q]);
    }
#pragma unroll
    for (int q = 0; q < TI; q++)
        *(ull*)&red[w][q][2 * lane] = o[q];
    __syncthreads();

    // ---- reduce partials + activation + residual ----
    if (tid < 128) {
        int r = tid >> 4, f4 = (tid & 15) * 4;
        float4 s0 = *(const float4*)&red[0][r][f4];
        float4 s1 = *(const float4*)&red[1][r][f4];
        float4 s2 = *(const float4*)&red[2][r][f4];
        float4 s3 = *(const float4*)&red[3][r][f4];
        float4 s4 = *(const float4*)&red[4][r][f4];
        float4 s5 = *(const float4*)&red[5][r][f4];
        float4 s6 = *(const float4*)&red[6][r][f4];
        float4 s7 = *(const float4*)&red[7][r][f4];
        float r0 = ((s0.x + s1.x) + (s2.x + s3.x)) + ((s4.x + s5.x) + (s6.x + s7.x));
        float r1 = ((s0.y + s1.y) + (s2.y + s3.y)) + ((s4.y + s5.y) + (s6.y + s7.y));
        float r2 = ((s0.z + s1.z) + (s2.z + s3.z)) + ((s4.z + s5.z) + (s6.z + s7.z));
        float r3 = ((s0.w + s1.w) + (s2.w + s3.w)) + ((s4.w + s5.w) + (s6.w + s7.w));
        if (mode == 0) {       // ELU (alpha=1)
            r0 = r0 > 0.f ? r0 : expm1f(r0);
            r1 = r1 > 0.f ? r1 : expm1f(r1);
            r2 = r2 > 0.f ? r2 : expm1f(r2);
            r3 = r3 > 0.f ? r3 : expm1f(r3);
        }
        int gi = i0 + r;
        float4 xi = *(const float4*)&x_in[gi * DIM + h * NF + f4];
        *(float4*)&x_out[gi * DIM + h * NF + f4] =
            make_float4(xi.x + r0, xi.y + r1, xi.z + r2, xi.w + r3);
    }
}

// ---------------------------------------------------------------------------
extern "C" void kernel_launch(void* const* d_in, const int* in_sizes, int n_in,
                              void* d_out, int out_size) {
    const float* x   = (const float*)d_in[0];
    const int*   adj = (const int*)  d_in[1];
    const float* Wl0 = (const float*)d_in[2];
    const float* Wr0 = (const float*)d_in[3];
    const float* a0  = (const float*)d_in[4];
    const float* Wl1 = (const float*)d_in[5];
    const float* Wr1 = (const float*)d_in[6];
    const float* a1  = (const float*)d_in[7];
    float* out = (float*)d_out;

    dim3 gg(NH, NN / BM, 2);      // (8, 24, 2) = 384 blocks
    dim3 ga(NN / TI, NH);         // (48, 8)    = 384 blocks

    // layer 0
    gemm_kernel<<<gg, 128>>>(x, Wl0, Wr0, a0, 0);
    attn_kernel<<<ga, 256>>>(a0, adj, x, out, 0);    // -> g_x1 (ELU + residual)
    // layer 1
    gemm_kernel<<<gg, 128>>>(x, Wl1, Wr1, a1, 1);
    attn_kernel<<<ga, 256>>>(a1, adj, x, out, 1);    // -> d_out (residual)
}

// round 8
// speedup vs baseline: 1.3038x; 1.0328x over previous
#include <cuda_runtime.h>
#include <math.h>

#define NN  384
#define DIM 512
#define NH  8
#define NF  64

typedef unsigned long long ull;

// ---------------- packed f32x2 helpers ----------------
__device__ __forceinline__ void unpack2(ull v, float& lo, float& hi) {
    asm("mov.b64 {%0, %1}, %2;" : "=f"(lo), "=f"(hi) : "l"(v));
}
__device__ __forceinline__ ull fma2(ull a, ull b, ull c) {
    ull d; asm("fma.rn.f32x2 %0, %1, %2, %3;" : "=l"(d) : "l"(a), "l"(b), "l"(c));
    return d;
}
__device__ __forceinline__ ull add2(ull a, ull b) {
    ull d; asm("add.rn.f32x2 %0, %1, %2;" : "=l"(d) : "l"(a), "l"(b));
    return d;
}
__device__ __forceinline__ ull abs2(ull v) { return v & 0x7FFFFFFF7FFFFFFFULL; }

// ---------------- scratch (device globals) ----------------
__device__ float g_glT[NH * NF * NN];  // transposed g_l: [h][f][j]
__device__ float g_gr[NN * DIM];
__device__ float g_c[2 * NH * NN];     // [which(l=0,r=1)][h][n]
__device__ float g_x1[NN * DIM];       // layer-0 output / layer-1 input

// =================== merged GEMM: both W_l and W_r per block ================
#define BM 16
#define BN 64
#define BK 32
#define BSTR 68    // Bs row stride (floats)
#define ASTR 18    // As2 row stride (float2)

__global__ void __launch_bounds__(128)
gemm_kernel(const float* __restrict__ Xp,
            const float* __restrict__ Wl,
            const float* __restrict__ Wr,
            const float* __restrict__ av,
            int use_x1) {
    const float* X = use_x1 ? g_x1 : Xp;
    int h  = blockIdx.x;
    int m0 = blockIdx.y * BM;
    int n0 = h * BN;

    __shared__ float2 As2[2][BK][ASTR];     //  9216 B (dup pairs, k-major)
    __shared__ float  Bsl[2][BK][BSTR];     // 17408 B
    __shared__ float  Bsr[2][BK][BSTR];     // 17408 B  total 44 KB

    int tid = threadIdx.x;
    int tx = tid & 15, ty = tid >> 4;

    int mX = tid >> 3, kqX = (tid & 7) * 4;          // X loader
    int rB = tid >> 3, cB = (tid & 7) * 4;           // W loader

    const float* xptr = X + (m0 + mX) * DIM + kqX;
    const float* wlp  = Wl + rB * DIM + n0 + cB;
    const float* wrp  = Wr + rB * DIM + n0 + cB;

    float4 xb, bl[4], br[4];
    xb = *(const float4*)xptr;
#pragma unroll
    for (int s = 0; s < 2; s++)
#pragma unroll
        for (int c = 0; c < 2; c++) {
            bl[s * 2 + c] = *(const float4*)(wlp + s * 16 * DIM + c * 32);
            br[s * 2 + c] = *(const float4*)(wrp + s * 16 * DIM + c * 32);
        }

    // stage tile 0 into buffer 0
    As2[0][kqX + 0][mX] = make_float2(xb.x, xb.x);
    As2[0][kqX + 1][mX] = make_float2(xb.y, xb.y);
    As2[0][kqX + 2][mX] = make_float2(xb.z, xb.z);
    As2[0][kqX + 3][mX] = make_float2(xb.w, xb.w);
#pragma unroll
    for (int s = 0; s < 2; s++)
#pragma unroll
        for (int c = 0; c < 2; c++) {
            *(float4*)&Bsl[0][rB + 16 * s][cB + c * 32] = bl[s * 2 + c];
            *(float4*)&Bsr[0][rB + 16 * s][cB + c * 32] = br[s * 2 + c];
        }

    ull al00 = 0, al01 = 0, al10 = 0, al11 = 0;   // W_l accumulators
    ull ar00 = 0, ar01 = 0, ar10 = 0, ar11 = 0;   // W_r accumulators

    const int NT = DIM / BK;     // 16
    int buf = 0;
    for (int t = 0; t < NT; t++) {
        __syncthreads();
        if (t + 1 < NT) {   // prefetch next tile to regs
            xb = *(const float4*)(xptr + (t + 1) * BK);
            const float* wl2 = wlp + (t + 1) * BK * DIM;
            const float* wr2 = wrp + (t + 1) * BK * DIM;
#pragma unroll
            for (int s = 0; s < 2; s++)
#pragma unroll
                for (int c = 0; c < 2; c++) {
                    bl[s * 2 + c] = *(const float4*)(wl2 + s * 16 * DIM + c * 32);
                    br[s * 2 + c] = *(const float4*)(wr2 + s * 16 * DIM + c * 32);
                }
        }
#pragma unroll
        for (int k = 0; k < BK; k++) {
            ulonglong2 pa = *(const ulonglong2*)&As2[buf][k][ty * 2];
            ulonglong2 pl = *(const ulonglong2*)&Bsl[buf][k][tx * 4];
            ulonglong2 pr = *(const ulonglong2*)&Bsr[buf][k][tx * 4];
            al00 = fma2(pa.x, pl.x, al00);
            al01 = fma2(pa.x, pl.y, al01);
            al10 = fma2(pa.y, pl.x, al10);
            al11 = fma2(pa.y, pl.y, al11);
            ar00 = fma2(pa.x, pr.x, ar00);
            ar01 = fma2(pa.x, pr.y, ar01);
            ar10 = fma2(pa.y, pr.x, ar10);
            ar11 = fma2(pa.y, pr.y, ar11);
        }
        if (t + 1 < NT) {
            int nb = buf ^ 1;
            As2[nb][kqX + 0][mX] = make_float2(xb.x, xb.x);
            As2[nb][kqX + 1][mX] = make_float2(xb.y, xb.y);
            As2[nb][kqX + 2][mX] = make_float2(xb.z, xb.z);
            As2[nb][kqX + 3][mX] = make_float2(xb.w, xb.w);
#pragma unroll
            for (int s = 0; s < 2; s++)
#pragma unroll
                for (int c = 0; c < 2; c++) {
                    *(float4*)&Bsl[nb][rB + 16 * s][cB + c * 32] = bl[s * 2 + c];
                    *(float4*)&Bsr[nb][rB + 16 * s][cB + c * 32] = br[s * 2 + c];
                }
        }
        buf ^= 1;
    }

    // ---- epilogue: unpack both tiles ----
    float l00, l01, l02, l03, l10, l11, l12, l13;
    float r00, r01, r02, r03, r10, r11, r12, r13;
    unpack2(al00, l00, l01); unpack2(al01, l02, l03);
    unpack2(al10, l10, l11); unpack2(al11, l12, l13);
    unpack2(ar00, r00, r01); unpack2(ar01, r02, r03);
    unpack2(ar10, r10, r11); unpack2(ar11, r12, r13);

    int row0 = m0 + ty * 2;
    // g_r row-major
    *(float4*)&g_gr[row0 * DIM + n0 + tx * 4]       = make_float4(r00, r01, r02, r03);
    *(float4*)&g_gr[(row0 + 1) * DIM + n0 + tx * 4] = make_float4(r10, r11, r12, r13);
    // g_l transposed [h][f][j]
    {
        float* gt = g_glT + (n0 + tx * 4) * NN + row0;
        *(float2*)(gt + 0 * NN) = make_float2(l00, l10);
        *(float2*)(gt + 1 * NN) = make_float2(l01, l11);
        *(float2*)(gt + 2 * NN) = make_float2(l02, l12);
        *(float2*)(gt + 3 * NN) = make_float2(l03, l13);
    }
    // fused c vectors (both l and r)
    float4 af = *(const float4*)&av[tx * 4];
    float cl0 = fmaf(af.x, l00, fmaf(af.y, l01, fmaf(af.z, l02, af.w * l03)));
    float cl1 = fmaf(af.x, l10, fmaf(af.y, l11, fmaf(af.z, l12, af.w * l13)));
    float cr0 = fmaf(af.x, r00, fmaf(af.y, r01, fmaf(af.z, r02, af.w * r03)));
    float cr1 = fmaf(af.x, r10, fmaf(af.y, r11, fmaf(af.z, r12, af.w * r13)));
#pragma unroll
    for (int o = 8; o; o >>= 1) {
        cl0 += __shfl_xor_sync(0xffffffffu, cl0, o);
        cl1 += __shfl_xor_sync(0xffffffffu, cl1, o);
        cr0 += __shfl_xor_sync(0xffffffffu, cr0, o);
        cr1 += __shfl_xor_sync(0xffffffffu, cr1, o);
    }
    if (tx == 0) {
        g_c[h * NN + row0]               = cl0;
        g_c[h * NN + row0 + 1]           = cl1;
        g_c[NH * NN + h * NN + row0]     = cr0;
        g_c[NH * NN + h * NN + row0 + 1] = cr1;
    }
}

// ======= fused attention (VERIFIED R4 structure: warp = 2 rows x half-j) ====
#define TI 8

__global__ void __launch_bounds__(256)
attn_kernel(const float* __restrict__ a,
            const int* __restrict__ adj,
            const float* __restrict__ x_in_p,
            float* __restrict__ x_out_p,
            int mode) {                       // 0: layer0 (ELU), 1: layer1
    __shared__ float2 att_t[NN][TI];          // duplicated (p,p): 24576 B
    __shared__ float  red[8][TI][NF + 4];     // 17408 B
    __shared__ float2 grdup[TI][NF];          //  4096 B
    __shared__ float2 a4dup[NF];              //   512 B
    __shared__ float2 ms[TI][2];              //   128 B   total ~46.7 KB

    const float* x_in = mode ? g_x1 : x_in_p;
    float* x_out      = mode ? x_out_p : g_x1;

    int h   = blockIdx.y;
    int i0  = blockIdx.x * TI;
    int tid = threadIdx.x, lane = tid & 31, w = tid >> 5;
    int rp  = w >> 1;               // row pair: rows 2rp, 2rp+1
    int jh  = w & 1;                // j half: [jh*192, jh*192+192)

    // ---- stage duplicated operand tables ----
    for (int t = tid; t < TI * NF; t += 256) {
        int r = t >> 6, f = t & 63;
        float v = g_gr[(i0 + r) * DIM + h * NF + f];
        grdup[r][f] = make_float2(v, v);
    }
    if (tid < NF) { float v = 0.4f * a[tid]; a4dup[tid] = make_float2(v, v); }
    __syncthreads();

    // ---- phase 1: acc[i][jpair] += 0.4a[f] * |g_r[i,f] + g_l[j,f]| ----
    ull acc2[2][3];
#pragma unroll
    for (int il = 0; il < 2; il++)
#pragma unroll
        for (int jt = 0; jt < 3; jt++) acc2[il][jt] = 0ULL;

    const float* glT = g_glT + h * (NF * NN) + jh * 192 + 2 * lane;

#pragma unroll 1
    for (int fc = 0; fc < 16; fc++) {
        ull pa[4], pg0[4], pg1[4];
#pragma unroll
        for (int f4 = 0; f4 < 4; f4++) {
            pa[f4]  = *(const ull*)&a4dup[fc * 4 + f4];
            pg0[f4] = *(const ull*)&grdup[rp * 2][fc * 4 + f4];
            pg1[f4] = *(const ull*)&grdup[rp * 2 + 1][fc * 4 + f4];
        }
#pragma unroll
        for (int f4 = 0; f4 < 4; f4++) {
            const float* gp = glT + (fc * 4 + f4) * NN;
#pragma unroll
            for (int jt = 0; jt < 3; jt++) {
                ull gl2 = *(const ull*)(gp + jt * 64);
                acc2[0][jt] = fma2(pa[f4], abs2(add2(pg0[f4], gl2)), acc2[0][jt]);
                acc2[1][jt] = fma2(pa[f4], abs2(add2(pg1[f4], gl2)), acc2[1][jt]);
            }
        }
    }

    // ---- split-j masked softmax: local (m,s), then cross-half combine ----
    const float* clv = g_c + h * NN;
    const float* crv = g_c + NH * NN + h * NN;
    float p[2][6], mh[2];
#pragma unroll
    for (int il = 0; il < 2; il++) {
        int row = rp * 2 + il;
        int i = i0 + row;
        float cr6 = 0.6f * crv[i];
        unsigned vm = 0;
        float m = -1e30f;
#pragma unroll
        for (int jt = 0; jt < 3; jt++) {
            int j0 = jh * 192 + jt * 64 + 2 * lane;
            float2 gcl = *(const float2*)(clv + j0);
            int2   adv = *(const int2*)(adj + i * NN + j0);
            float u0, u1; unpack2(acc2[il][jt], u0, u1);
            float e0 = cr6 + fmaf(0.6f, gcl.x, u0);
            float e1 = cr6 + fmaf(0.6f, gcl.y, u1);
            p[il][jt * 2] = e0; p[il][jt * 2 + 1] = e1;
            if (adv.x || (j0 == i))     { vm |= 1u << (jt * 2);     m = fmaxf(m, e0); }
            if (adv.y || (j0 + 1 == i)) { vm |= 1u << (jt * 2 + 1); m = fmaxf(m, e1); }
        }
#pragma unroll
        for (int o = 16; o; o >>= 1) m = fmaxf(m, __shfl_xor_sync(0xffffffffu, m, o));
        float s = 0.f;
#pragma unroll
        for (int q = 0; q < 6; q++) {
            float pv = ((vm >> q) & 1) ? __expf(p[il][q] - m) : 0.f;
            p[il][q] = pv; s += pv;
        }
#pragma unroll
        for (int o = 16; o; o >>= 1) s += __shfl_xor_sync(0xffffffffu, s, o);
        mh[il] = m;
        if (lane == 0) ms[row][jh] = make_float2(m, s);
    }
    __syncthreads();

#pragma unroll
    for (int il = 0; il < 2; il++) {
        int row = rp * 2 + il;
        float2 v0 = ms[row][0], v1 = ms[row][1];
        float M = fmaxf(v0.x, v1.x);
        float S = v0.y * __expf(v0.x - M) + v1.y * __expf(v1.x - M);
        float scale = __expf(mh[il] - M) / S;
#pragma unroll
        for (int jt = 0; jt < 3; jt++) {
            int j0 = jh * 192 + jt * 64 + 2 * lane;
            float p0 = p[il][jt * 2] * scale;
            float p1 = p[il][jt * 2 + 1] * scale;
            att_t[j0][row]     = make_float2(p0, p0);
            att_t[j0 + 1][row] = make_float2(p1, p1);
        }
    }
    __syncthreads();

    // ---- phase 2: warp owns 48 j, accumulates all 8 rows for its f-pair ----
    ull o[TI];
#pragma unroll
    for (int q = 0; q < TI; q++) o[q] = 0ULL;

    const float* grp = g_gr + h * NF + 2 * lane;
    int jstart = w * 48;
#pragma unroll 4
    for (int jj = 0; jj < 48; jj++) {
        int j = jstart + jj;
        ull gp = *(const ull*)(grp + j * DIM);
#pragma unroll
        for (int q = 0; q < TI; q++)
            o[q] = fma2(*(const ull*)&att_t[j][q], gp, o[q]);
    }
#pragma unroll
    for (int q = 0; q < TI; q++)
        *(ull*)&red[w][q][2 * lane] = o[q];
    __syncthreads();

    // ---- reduce partials + activation + residual ----
    if (tid < 128) {
        int r = tid >> 4, f4 = (tid & 15) * 4;
        float4 s0 = *(const float4*)&red[0][r][f4];
        float4 s1 = *(const float4*)&red[1][r][f4];
        float4 s2 = *(const float4*)&red[2][r][f4];
        float4 s3 = *(const float4*)&red[3][r][f4];
        float4 s4 = *(const float4*)&red[4][r][f4];
        float4 s5 = *(const float4*)&red[5][r][f4];
        float4 s6 = *(const float4*)&red[6][r][f4];
        float4 s7 = *(const float4*)&red[7][r][f4];
        float r0 = ((s0.x + s1.x) + (s2.x + s3.x)) + ((s4.x + s5.x) + (s6.x + s7.x));
        float r1 = ((s0.y + s1.y) + (s2.y + s3.y)) + ((s4.y + s5.y) + (s6.y + s7.y));
        float r2 = ((s0.z + s1.z) + (s2.z + s3.z)) + ((s4.z + s5.z) + (s6.z + s7.z));
        float r3 = ((s0.w + s1.w) + (s2.w + s3.w)) + ((s4.w + s5.w) + (s6.w + s7.w));
        if (mode == 0) {       // ELU (alpha=1)
            r0 = r0 > 0.f ? r0 : expm1f(r0);
            r1 = r1 > 0.f ? r1 : expm1f(r1);
            r2 = r2 > 0.f ? r2 : expm1f(r2);
            r3 = r3 > 0.f ? r3 : expm1f(r3);
        }
        int gi = i0 + r;
        float4 xi = *(const float4*)&x_in[gi * DIM + h * NF + f4];
        *(float4*)&x_out[gi * DIM + h * NF + f4] =
            make_float4(xi.x + r0, xi.y + r1, xi.z + r2, xi.w + r3);
    }
}

// ---------------------------------------------------------------------------
extern "C" void kernel_launch(void* const* d_in, const int* in_sizes, int n_in,
                              void* d_out, int out_size) {
    const float* x   = (const float*)d_in[0];
    const int*   adj = (const int*)  d_in[1];
    const float* Wl0 = (const float*)d_in[2];
    const float* Wr0 = (const float*)d_in[3];
    const float* a0  = (const float*)d_in[4];
    const float* Wl1 = (const float*)d_in[5];
    const float* Wr1 = (const float*)d_in[6];
    const float* a1  = (const float*)d_in[7];
    float* out = (float*)d_out;

    dim3 gg(NH, NN / BM);         // (8, 24) = 192 blocks
    dim3 ga(NN / TI, NH);         // (48, 8) = 384 blocks

    // layer 0
    gemm_kernel<<<gg, 128>>>(x, Wl0, Wr0, a0, 0);
    attn_kernel<<<ga, 256>>>(a0, adj, x, out, 0);    // -> g_x1 (ELU + residual)
    // layer 1
    gemm_kernel<<<gg, 128>>>(x, Wl1, Wr1, a1, 1);
    attn_kernel<<<ga, 256>>>(a1, adj, x, out, 1);    // -> d_out (residual)
}

// round 12
// speedup vs baseline: 1.4300x; 1.0968x over previous
#include <cuda_runtime.h>
#include <math.h>

#define NN  384
#define DIM 512
#define NH  8
#define NF  64

typedef unsigned long long ull;

// ---------------- packed f32x2 helpers ----------------
__device__ __forceinline__ void unpack2(ull v, float& lo, float& hi) {
    asm("mov.b64 {%0, %1}, %2;" : "=f"(lo), "=f"(hi) : "l"(v));
}
__device__ __forceinline__ ull fma2(ull a, ull b, ull c) {
    ull d; asm("fma.rn.f32x2 %0, %1, %2, %3;" : "=l"(d) : "l"(a), "l"(b), "l"(c));
    return d;
}
__device__ __forceinline__ ull add2(ull a, ull b) {
    ull d; asm("add.rn.f32x2 %0, %1, %2;" : "=l"(d) : "l"(a), "l"(b));
    return d;
}
__device__ __forceinline__ ull abs2(ull v) { return v & 0x7FFFFFFF7FFFFFFFULL; }

// ---------------- scratch (device globals) ----------------
__device__ float g_glT[NH * NF * NN];     // transposed g_l: [h][f][j]
__device__ float g_gr[NN * DIM];
__device__ float g_c[2 * NH * NN];        // [lr(l=0,r=1)][h][n]
__device__ float g_x1[NN * DIM];          // layer-0 output / layer-1 input
__device__ float g_part[2][2][NN * DIM];  // split-K partials [kh][mat(l=0,r=1)]

// =================== split-K GEMM: both W_l and W_r per block ===============
#define BM 16
#define BN 64
#define BK 32
#define KH 2        // k-split factor
#define KSEG (DIM / KH)   // 256
#define BSTR 68     // Bs row stride (floats)
#define ASTR 18     // As2 row stride (float2)

__global__ void __launch_bounds__(128)
gemm_kernel(const float* __restrict__ Xp,
            const float* __restrict__ Wl,
            const float* __restrict__ Wr,
            int use_x1) {
    const float* X = use_x1 ? g_x1 : Xp;
    int h  = blockIdx.x;
    int m0 = blockIdx.y * BM;
    int kh = blockIdx.z;
    int n0 = h * BN;
    int k0 = kh * KSEG;

    __shared__ float2 As2[2][BK][ASTR];     //  9216 B (dup pairs, k-major)
    __shared__ float  Bsl[2][BK][BSTR];     // 17408 B
    __shared__ float  Bsr[2][BK][BSTR];     // 17408 B

    int tid = threadIdx.x;
    int tx = tid & 15, ty = tid >> 4;

    int mX = tid >> 3, kqX = (tid & 7) * 4;          // X loader
    int rB = tid >> 3, cB = (tid & 7) * 4;           // W loader

    const float* xptr = X + (m0 + mX) * DIM + k0 + kqX;
    const float* wlp  = Wl + (k0 + rB) * DIM + n0 + cB;
    const float* wrp  = Wr + (k0 + rB) * DIM + n0 + cB;

    float4 xb, bl[4], br[4];
    xb = *(const float4*)xptr;
#pragma unroll
    for (int s = 0; s < 2; s++)
#pragma unroll
        for (int c = 0; c < 2; c++) {
            bl[s * 2 + c] = *(const float4*)(wlp + s * 16 * DIM + c * 32);
            br[s * 2 + c] = *(const float4*)(wrp + s * 16 * DIM + c * 32);
        }

    // stage tile 0 into buffer 0
    As2[0][kqX + 0][mX] = make_float2(xb.x, xb.x);
    As2[0][kqX + 1][mX] = make_float2(xb.y, xb.y);
    As2[0][kqX + 2][mX] = make_float2(xb.z, xb.z);
    As2[0][kqX + 3][mX] = make_float2(xb.w, xb.w);
#pragma unroll
    for (int s = 0; s < 2; s++)
#pragma unroll
        for (int c = 0; c < 2; c++) {
            *(float4*)&Bsl[0][rB + 16 * s][cB + c * 32] = bl[s * 2 + c];
            *(float4*)&Bsr[0][rB + 16 * s][cB + c * 32] = br[s * 2 + c];
        }

    ull al00 = 0, al01 = 0, al10 = 0, al11 = 0;   // W_l accumulators
    ull ar00 = 0, ar01 = 0, ar10 = 0, ar11 = 0;   // W_r accumulators

    const int NT = KSEG / BK;     // 8
    int buf = 0;
    for (int t = 0; t < NT; t++) {
        __syncthreads();
        if (t + 1 < NT) {   // prefetch next tile to regs
            xb = *(const float4*)(xptr + (t + 1) * BK);
            const float* wl2 = wlp + (t + 1) * BK * DIM;
            const float* wr2 = wrp + (t + 1) * BK * DIM;
#pragma unroll
            for (int s = 0; s < 2; s++)
#pragma unroll
                for (int c = 0; c < 2; c++) {
                    bl[s * 2 + c] = *(const float4*)(wl2 + s * 16 * DIM + c * 32);
                    br[s * 2 + c] = *(const float4*)(wr2 + s * 16 * DIM + c * 32);
                }
        }
#pragma unroll
        for (int k = 0; k < BK; k++) {
            ulonglong2 pa = *(const ulonglong2*)&As2[buf][k][ty * 2];
            ulonglong2 pl = *(const ulonglong2*)&Bsl[buf][k][tx * 4];
            ulonglong2 pr = *(const ulonglong2*)&Bsr[buf][k][tx * 4];
            al00 = fma2(pa.x, pl.x, al00);
            al01 = fma2(pa.x, pl.y, al01);
            al10 = fma2(pa.y, pl.x, al10);
            al11 = fma2(pa.y, pl.y, al11);
            ar00 = fma2(pa.x, pr.x, ar00);
            ar01 = fma2(pa.x, pr.y, ar01);
            ar10 = fma2(pa.y, pr.x, ar10);
            ar11 = fma2(pa.y, pr.y, ar11);
        }
        if (t + 1 < NT) {
            int nb = buf ^ 1;
            As2[nb][kqX + 0][mX] = make_float2(xb.x, xb.x);
            As2[nb][kqX + 1][mX] = make_float2(xb.y, xb.y);
            As2[nb][kqX + 2][mX] = make_float2(xb.z, xb.z);
            As2[nb][kqX + 3][mX] = make_float2(xb.w, xb.w);
#pragma unroll
            for (int s = 0; s < 2; s++)
#pragma unroll
                for (int c = 0; c < 2; c++) {
                    *(float4*)&Bsl[nb][rB + 16 * s][cB + c * 32] = bl[s * 2 + c];
                    *(float4*)&Bsr[nb][rB + 16 * s][cB + c * 32] = br[s * 2 + c];
                }
        }
        buf ^= 1;
    }

    // ---- epilogue: raw partial stores (packed pairs are already contiguous) -
    int row0 = m0 + ty * 2;
    int idx0 = row0 * DIM + n0 + tx * 4;
    ulonglong2 vl0; vl0.x = al00; vl0.y = al01;
    ulonglong2 vl1; vl1.x = al10; vl1.y = al11;
    ulonglong2 vr0; vr0.x = ar00; vr0.y = ar01;
    ulonglong2 vr1; vr1.x = ar10; vr1.y = ar11;
    *(ulonglong2*)&g_part[kh][0][idx0]       = vl0;
    *(ulonglong2*)&g_part[kh][0][idx0 + DIM] = vl1;
    *(ulonglong2*)&g_part[kh][1][idx0]       = vr0;
    *(ulonglong2*)&g_part[kh][1][idx0 + DIM] = vr1;
}

// ====== reduce: sum k-halves, emit g_gr, transposed g_glT, both c vectors ===
#define RR 16   // rows per reduce block

__global__ void __launch_bounds__(256)
reduce_kernel(const float* __restrict__ av) {
    __shared__ float sgl[RR][NF + 4];
    __shared__ float sgr[RR][NF + 4];

    int h  = blockIdx.y;
    int i0 = blockIdx.x * RR;
    int n0 = h * BN;
    int tid = threadIdx.x, lane = tid & 31, w = tid >> 5;

    // phase A: sum partials; g_gr straight out; g_l into smem for transpose
    {
        int r = tid >> 4, fq = (tid & 15) * 4;
        int idx = (i0 + r) * DIM + n0 + fq;
        float4 l0 = *(const float4*)&g_part[0][0][idx];
        float4 l1 = *(const float4*)&g_part[1][0][idx];
        float4 r0 = *(const float4*)&g_part[0][1][idx];
        float4 r1 = *(const float4*)&g_part[1][1][idx];
        float4 gl = make_float4(l0.x + l1.x, l0.y + l1.y, l0.z + l1.z, l0.w + l1.w);
        float4 gr = make_float4(r0.x + r1.x, r0.y + r1.y, r0.z + r1.z, r0.w + r1.w);
        *(float4*)&g_gr[idx] = gr;
        *(float4*)&sgl[r][fq] = gl;
        *(float4*)&sgr[r][fq] = gr;
    }
    __syncthreads();

    // phase B1: transposed g_glT store (coalesced over j)
    {
        int f = tid >> 2, jq = (tid & 3) * 4;
        float4 v = make_float4(sgl[jq][f], sgl[jq + 1][f], sgl[jq + 2][f], sgl[jq + 3][f]);
        *(float4*)&g_glT[(h * NF + f) * NN + i0 + jq] = v;
    }

    // phase B2: c vectors — warp w handles rows 2w, 2w+1
    float a1v = av[lane], a2v = av[lane + 32];
#pragma unroll
    for (int il = 0; il < 2; il++) {
        int row = 2 * w + il;
        float cl = fmaf(a1v, sgl[row][lane], a2v * sgl[row][lane + 32]);
        float cr = fmaf(a1v, sgr[row][lane], a2v * sgr[row][lane + 32]);
#pragma unroll
        for (int o = 16; o; o >>= 1) {
            cl += __shfl_xor_sync(0xffffffffu, cl, o);
            cr += __shfl_xor_sync(0xffffffffu, cr, o);
        }
        if (lane == 0) {
            g_c[h * NN + i0 + row]           = cl;
            g_c[NH * NN + h * NN + i0 + row] = cr;
        }
    }
}

// ======= fused attention (VERIFIED R8 structure: warp = 2 rows x half-j) ====
#define TI 8

__global__ void __launch_bounds__(256)
attn_kernel(const float* __restrict__ a,
            const int* __restrict__ adj,
            const float* __restrict__ x_in_p,
            float* __restrict__ x_out_p,
            int mode) {                       // 0: layer0 (ELU), 1: layer1
    __shared__ float2 att_t[NN][TI];          // duplicated (p,p): 24576 B
    __shared__ float  red[8][TI][NF + 4];     // 17408 B
    __shared__ float2 grdup[TI][NF];          //  4096 B
    __shared__ float2 a4dup[NF];              //   512 B
    __shared__ float2 ms[TI][2];              //   128 B

    const float* x_in = mode ? g_x1 : x_in_p;
    float* x_out      = mode ? x_out_p : g_x1;

    int h   = blockIdx.y;
    int i0  = blockIdx.x * TI;
    int tid = threadIdx.x, lane = tid & 31, w = tid >> 5;
    int rp  = w >> 1;               // row pair: rows 2rp, 2rp+1
    int jh  = w & 1;                // j half: [jh*192, jh*192+192)

    // ---- stage duplicated operand tables ----
    for (int t = tid; t < TI * NF; t += 256) {
        int r = t >> 6, f = t & 63;
        float v = g_gr[(i0 + r) * DIM + h * NF + f];
        grdup[r][f] = make_float2(v, v);
    }
    if (tid < NF) { float v = 0.4f * a[tid]; a4dup[tid] = make_float2(v, v); }
    __syncthreads();

    // ---- phase 1: acc[i][jpair] += 0.4a[f] * |g_r[i,f] + g_l[j,f]| ----
    ull acc2[2][3];
#pragma unroll
    for (int il = 0; il < 2; il++)
#pragma unroll
        for (int jt = 0; jt < 3; jt++) acc2[il][jt] = 0ULL;

    const float* glT = g_glT + h * (NF * NN) + jh * 192 + 2 * lane;

#pragma unroll 1
    for (int fc = 0; fc < 16; fc++) {
        ull pa[4], pg0[4], pg1[4];
#pragma unroll
        for (int f4 = 0; f4 < 4; f4++) {
            pa[f4]  = *(const ull*)&a4dup[fc * 4 + f4];
            pg0[f4] = *(const ull*)&grdup[rp * 2][fc * 4 + f4];
            pg1[f4] = *(const ull*)&grdup[rp * 2 + 1][fc * 4 + f4];
        }
#pragma unroll
        for (int f4 = 0; f4 < 4; f4++) {
            const float* gp = glT + (fc * 4 + f4) * NN;
#pragma unroll
            for (int jt = 0; jt < 3; jt++) {
                ull gl2 = *(const ull*)(gp + jt * 64);
                acc2[0][jt] = fma2(pa[f4], abs2(add2(pg0[f4], gl2)), acc2[0][jt]);
                acc2[1][jt] = fma2(pa[f4], abs2(add2(pg1[f4], gl2)), acc2[1][jt]);
            }
        }
    }

    // ---- split-j masked softmax: local (m,s), then cross-half combine ----
    const float* clv = g_c + h * NN;
    const float* crv = g_c + NH * NN + h * NN;
    float p[2][6], mh[2];
#pragma unroll
    for (int il = 0; il < 2; il++) {
        int row = rp * 2 + il;
        int i = i0 + row;
        float cr6 = 0.6f * crv[i];
        unsigned vm = 0;
        float m = -1e30f;
#pragma unroll
        for (int jt = 0; jt < 3; jt++) {
            int j0 = jh * 192 + jt * 64 + 2 * lane;
            float2 gcl = *(const float2*)(clv + j0);
            int2   adv = *(const int2*)(adj + i * NN + j0);
            float u0, u1; unpack2(acc2[il][jt], u0, u1);
            float e0 = cr6 + fmaf(0.6f, gcl.x, u0);
            float e1 = cr6 + fmaf(0.6f, gcl.y, u1);
            p[il][jt * 2] = e0; p[il][jt * 2 + 1] = e1;
            if (adv.x || (j0 == i))     { vm |= 1u << (jt * 2);     m = fmaxf(m, e0); }
            if (adv.y || (j0 + 1 == i)) { vm |= 1u << (jt * 2 + 1); m = fmaxf(m, e1); }
        }
#pragma unroll
        for (int o = 16; o; o >>= 1) m = fmaxf(m, __shfl_xor_sync(0xffffffffu, m, o));
        float s = 0.f;
#pragma unroll
        for (int q = 0; q < 6; q++) {
            float pv = ((vm >> q) & 1) ? __expf(p[il][q] - m) : 0.f;
            p[il][q] = pv; s += pv;
        }
#pragma unroll
        for (int o = 16; o; o >>= 1) s += __shfl_xor_sync(0xffffffffu, s, o);
        mh[il] = m;
        if (lane == 0) ms[row][jh] = make_float2(m, s);
    }
    __syncthreads();

#pragma unroll
    for (int il = 0; il < 2; il++) {
        int row = rp * 2 + il;
        float2 v0 = ms[row][0], v1 = ms[row][1];
        float M = fmaxf(v0.x, v1.x);
        float S = v0.y * __expf(v0.x - M) + v1.y * __expf(v1.x - M);
        float scale = __expf(mh[il] - M) / S;
#pragma unroll
        for (int jt = 0; jt < 3; jt++) {
            int j0 = jh * 192 + jt * 64 + 2 * lane;
            float p0 = p[il][jt * 2] * scale;
            float p1 = p[il][jt * 2 + 1] * scale;
            att_t[j0][row]     = make_float2(p0, p0);
            att_t[j0 + 1][row] = make_float2(p1, p1);
        }
    }
    __syncthreads();

    // ---- phase 2: warp owns 48 j, accumulates all 8 rows for its f-pair ----
    ull o[TI];
#pragma unroll
    for (int q = 0; q < TI; q++) o[q] = 0ULL;

    const float* grp = g_gr + h * NF + 2 * lane;
    int jstart = w * 48;
#pragma unroll 4
    for (int jj = 0; jj < 48; jj++) {
        int j = jstart + jj;
        ull gp = *(const ull*)(grp + j * DIM);
#pragma unroll
        for (int q = 0; q < TI; q++)
            o[q] = fma2(*(const ull*)&att_t[j][q], gp, o[q]);
    }
#pragma unroll
    for (int q = 0; q < TI; q++)
        *(ull*)&red[w][q][2 * lane] = o[q];
    __syncthreads();

    // ---- reduce partials + activation + residual ----
    if (tid < 128) {
        int r = tid >> 4, f4 = (tid & 15) * 4;
        float4 s0 = *(const float4*)&red[0][r][f4];
        float4 s1 = *(const float4*)&red[1][r][f4];
        float4 s2 = *(const float4*)&red[2][r][f4];
        float4 s3 = *(const float4*)&red[3][r][f4];
        float4 s4 = *(const float4*)&red[4][r][f4];
        float4 s5 = *(const float4*)&red[5][r][f4];
        float4 s6 = *(const float4*)&red[6][r][f4];
        float4 s7 = *(const float4*)&red[7][r][f4];
        float r0 = ((s0.x + s1.x) + (s2.x + s3.x)) + ((s4.x + s5.x) + (s6.x + s7.x));
        float r1 = ((s0.y + s1.y) + (s2.y + s3.y)) + ((s4.y + s5.y) + (s6.y + s7.y));
        float r2 = ((s0.z + s1.z) + (s2.z + s3.z)) + ((s4.z + s5.z) + (s6.z + s7.z));
        float r3 = ((s0.w + s1.w) + (s2.w + s3.w)) + ((s4.w + s5.w) + (s6.w + s7.w));
        if (mode == 0) {       // ELU (alpha=1)
            r0 = r0 > 0.f ? r0 : expm1f(r0);
            r1 = r1 > 0.f ? r1 : expm1f(r1);
            r2 = r2 > 0.f ? r2 : expm1f(r2);
            r3 = r3 > 0.f ? r3 : expm1f(r3);
        }
        int gi = i0 + r;
        float4 xi = *(const float4*)&x_in[gi * DIM + h * NF + f4];
        *(float4*)&x_out[gi * DIM + h * NF + f4] =
            make_float4(xi.x + r0, xi.y + r1, xi.z + r2, xi.w + r3);
    }
}

// ---------------------------------------------------------------------------
extern "C" void kernel_launch(void* const* d_in, const int* in_sizes, int n_in,
                              void* d_out, int out_size) {
    const float* x   = (const float*)d_in[0];
    const int*   adj = (const int*)  d_in[1];
    const float* Wl0 = (const float*)d_in[2];
    const float* Wr0 = (const float*)d_in[3];
    const float* a0  = (const float*)d_in[4];
    const float* Wl1 = (const float*)d_in[5];
    const float* Wr1 = (const float*)d_in[6];
    const float* a1  = (const float*)d_in[7];
    float* out = (float*)d_out;

    dim3 gg(NH, NN / BM, KH);     // (8, 24, 2) = 384 blocks
    dim3 gr2(NN / RR, NH);        // (24, 8)
    dim3 ga(NN / TI, NH);         // (48, 8)    = 384 blocks

    // layer 0
    gemm_kernel<<<gg, 128>>>(x, Wl0, Wr0, 0);
    reduce_kernel<<<gr2, 256>>>(a0);
    attn_kernel<<<ga, 256>>>(a0, adj, x, out, 0);    // -> g_x1 (ELU + residual)
    // layer 1
    gemm_kernel<<<gg, 128>>>(x, Wl1, Wr1, 1);
    reduce_kernel<<<gr2, 256>>>(a1);
    attn_kernel<<<ga, 256>>>(a1, adj, x, out, 1);    // -> d_out (residual)
}

// round 13
// speedup vs baseline: 1.5866x; 1.1095x over previous
#include <cuda_runtime.h>
#include <math.h>

#define NN  384
#define DIM 512
#define NH  8
#define NF  64

typedef unsigned long long ull;

// ---------------- packed f32x2 helpers ----------------
__device__ __forceinline__ void unpack2(ull v, float& lo, float& hi) {
    asm("mov.b64 {%0, %1}, %2;" : "=f"(lo), "=f"(hi) : "l"(v));
}
__device__ __forceinline__ ull fma2(ull a, ull b, ull c) {
    ull d; asm("fma.rn.f32x2 %0, %1, %2, %3;" : "=l"(d) : "l"(a), "l"(b), "l"(c));
    return d;
}
__device__ __forceinline__ ull add2(ull a, ull b) {
    ull d; asm("add.rn.f32x2 %0, %1, %2;" : "=l"(d) : "l"(a), "l"(b));
    return d;
}
__device__ __forceinline__ ull abs2(ull v) { return v & 0x7FFFFFFF7FFFFFFFULL; }

// ---------------- scratch (device globals) ----------------
__device__ float g_glT[NH * NF * NN];     // transposed g_l: [h][f][j]
__device__ float g_gr[NN * DIM];
__device__ float g_c[2 * NH * NN];        // [lr(l=0,r=1)][h][n]
__device__ float g_x1[NN * DIM];          // layer-0 output / layer-1 input
__device__ float g_part[4][2][NN * DIM];  // split-K partials [kh][mat(l=0,r=1)]

// ========== split-K GEMM: thread = 4Mx8N of ONE matrix; 2 B/MAC LDS ==========
#define BM 32
#define BN 64
#define BK 16
#define KH 4
#define KSEG (DIM / KH)   // 128

__global__ void __launch_bounds__(128)
gemm_kernel(const float* __restrict__ Xp,
            const float* __restrict__ Wl,
            const float* __restrict__ Wr,
            int use_x1) {
    const float* X = use_x1 ? g_x1 : Xp;
    int h  = blockIdx.x;
    int m0 = blockIdx.y * BM;
    int kh = blockIdx.z;
    int n0 = h * BN;
    int k0 = kh * KSEG;

    __shared__ float2 As2[2][BK][BM + 2];     //  8704 B (dup pairs, k-major)
    __shared__ float  Bs[2][2][BK][BN + 4];   // 17408 B ([buf][mat][k][n])

    int tid = threadIdx.x;
    int mat = tid >> 6;            // 0: W_l, 1: W_r
    int tx  = tid & 7;             // cols tx*4..+3 and tx*4+32..+35
    int ty  = (tid >> 3) & 7;      // rows ty*4..+3

    int mA = tid >> 2, kA = (tid & 3) * 4;           // X loader
    int tB = tid & 63, rB = tB >> 2, cB = (tB & 3) * 16;   // W loader

    const float* xptr = X + (m0 + mA) * DIM + k0 + kA;
    const float* Wm   = mat ? Wr : Wl;
    const float* wptr = Wm + (k0 + rB) * DIM + n0 + cB;

    float4 xb  = *(const float4*)xptr;
    float4 bb0 = *(const float4*)(wptr);
    float4 bb1 = *(const float4*)(wptr + 4);
    float4 bb2 = *(const float4*)(wptr + 8);
    float4 bb3 = *(const float4*)(wptr + 12);

    // stage tile 0 into buffer 0
    As2[0][kA + 0][mA] = make_float2(xb.x, xb.x);
    As2[0][kA + 1][mA] = make_float2(xb.y, xb.y);
    As2[0][kA + 2][mA] = make_float2(xb.z, xb.z);
    As2[0][kA + 3][mA] = make_float2(xb.w, xb.w);
    *(float4*)&Bs[0][mat][rB][cB + 0]  = bb0;
    *(float4*)&Bs[0][mat][rB][cB + 4]  = bb1;
    *(float4*)&Bs[0][mat][rB][cB + 8]  = bb2;
    *(float4*)&Bs[0][mat][rB][cB + 12] = bb3;

    ull acc[4][4];
#pragma unroll
    for (int r = 0; r < 4; r++)
#pragma unroll
        for (int c = 0; c < 4; c++) acc[r][c] = 0ULL;

    const int NT = KSEG / BK;     // 8
    int buf = 0;
    for (int t = 0; t < NT; t++) {
        __syncthreads();
        if (t + 1 < NT) {   // prefetch next tile to regs
            xb = *(const float4*)(xptr + (t + 1) * BK);
            const float* wn = wptr + (t + 1) * BK * DIM;
            bb0 = *(const float4*)(wn);
            bb1 = *(const float4*)(wn + 4);
            bb2 = *(const float4*)(wn + 8);
            bb3 = *(const float4*)(wn + 12);
        }
#pragma unroll
        for (int k = 0; k < BK; k++) {
            ulonglong2 pa0 = *(const ulonglong2*)&As2[buf][k][ty * 4];
            ulonglong2 pa1 = *(const ulonglong2*)&As2[buf][k][ty * 4 + 2];
            ulonglong2 pb0 = *(const ulonglong2*)&Bs[buf][mat][k][tx * 4];
            ulonglong2 pb1 = *(const ulonglong2*)&Bs[buf][mat][k][tx * 4 + 32];
            acc[0][0] = fma2(pa0.x, pb0.x, acc[0][0]);
            acc[0][1] = fma2(pa0.x, pb0.y, acc[0][1]);
            acc[0][2] = fma2(pa0.x, pb1.x, acc[0][2]);
            acc[0][3] = fma2(pa0.x, pb1.y, acc[0][3]);
            acc[1][0] = fma2(pa0.y, pb0.x, acc[1][0]);
            acc[1][1] = fma2(pa0.y, pb0.y, acc[1][1]);
            acc[1][2] = fma2(pa0.y, pb1.x, acc[1][2]);
            acc[1][3] = fma2(pa0.y, pb1.y, acc[1][3]);
            acc[2][0] = fma2(pa1.x, pb0.x, acc[2][0]);
            acc[2][1] = fma2(pa1.x, pb0.y, acc[2][1]);
            acc[2][2] = fma2(pa1.x, pb1.x, acc[2][2]);
            acc[2][3] = fma2(pa1.x, pb1.y, acc[2][3]);
            acc[3][0] = fma2(pa1.y, pb0.x, acc[3][0]);
            acc[3][1] = fma2(pa1.y, pb0.y, acc[3][1]);
            acc[3][2] = fma2(pa1.y, pb1.x, acc[3][2]);
            acc[3][3] = fma2(pa1.y, pb1.y, acc[3][3]);
        }
        if (t + 1 < NT) {
            int nb = buf ^ 1;
            As2[nb][kA + 0][mA] = make_float2(xb.x, xb.x);
            As2[nb][kA + 1][mA] = make_float2(xb.y, xb.y);
            As2[nb][kA + 2][mA] = make_float2(xb.z, xb.z);
            As2[nb][kA + 3][mA] = make_float2(xb.w, xb.w);
            *(float4*)&Bs[nb][mat][rB][cB + 0]  = bb0;
            *(float4*)&Bs[nb][mat][rB][cB + 4]  = bb1;
            *(float4*)&Bs[nb][mat][rB][cB + 8]  = bb2;
            *(float4*)&Bs[nb][mat][rB][cB + 12] = bb3;
        }
        buf ^= 1;
    }

    // ---- epilogue: raw partial stores (packed pairs already contiguous) ----
#pragma unroll
    for (int r = 0; r < 4; r++) {
        int row = m0 + ty * 4 + r;
        int idx = row * DIM + n0 + tx * 4;
        ulonglong2 v0; v0.x = acc[r][0]; v0.y = acc[r][1];
        ulonglong2 v1; v1.x = acc[r][2]; v1.y = acc[r][3];
        *(ulonglong2*)&g_part[kh][mat][idx]      = v0;
        *(ulonglong2*)&g_part[kh][mat][idx + 32] = v1;
    }
}

// ====== reduce: sum k-quarters, emit g_gr, transposed g_glT, c vectors ======
#define RR 16   // rows per reduce block

__global__ void __launch_bounds__(256)
reduce_kernel(const float* __restrict__ av) {
    __shared__ float sgl[RR][NF + 4];
    __shared__ float sgr[RR][NF + 4];

    int h  = blockIdx.y;
    int i0 = blockIdx.x * RR;
    int n0 = h * BN;
    int tid = threadIdx.x, lane = tid & 31, w = tid >> 5;

    // phase A: sum partials; g_gr straight out; g_l into smem for transpose
    {
        int r = tid >> 4, fq = (tid & 15) * 4;
        int idx = (i0 + r) * DIM + n0 + fq;
        float4 gl = *(const float4*)&g_part[0][0][idx];
        float4 gr = *(const float4*)&g_part[0][1][idx];
#pragma unroll
        for (int kh = 1; kh < KH; kh++) {
            float4 l = *(const float4*)&g_part[kh][0][idx];
            float4 rr = *(const float4*)&g_part[kh][1][idx];
            gl.x += l.x;  gl.y += l.y;  gl.z += l.z;  gl.w += l.w;
            gr.x += rr.x; gr.y += rr.y; gr.z += rr.z; gr.w += rr.w;
        }
        *(float4*)&g_gr[idx]  = gr;
        *(float4*)&sgl[r][fq] = gl;
        *(float4*)&sgr[r][fq] = gr;
    }
    __syncthreads();

    // phase B1: transposed g_glT store (coalesced over j)
    {
        int f = tid >> 2, jq = (tid & 3) * 4;
        float4 v = make_float4(sgl[jq][f], sgl[jq + 1][f], sgl[jq + 2][f], sgl[jq + 3][f]);
        *(float4*)&g_glT[(h * NF + f) * NN + i0 + jq] = v;
    }

    // phase B2: c vectors — warp w handles rows 2w, 2w+1
    float a1v = av[lane], a2v = av[lane + 32];
#pragma unroll
    for (int il = 0; il < 2; il++) {
        int row = 2 * w + il;
        float cl = fmaf(a1v, sgl[row][lane], a2v * sgl[row][lane + 32]);
        float cr = fmaf(a1v, sgr[row][lane], a2v * sgr[row][lane + 32]);
#pragma unroll
        for (int o = 16; o; o >>= 1) {
            cl += __shfl_xor_sync(0xffffffffu, cl, o);
            cr += __shfl_xor_sync(0xffffffffu, cr, o);
        }
        if (lane == 0) {
            g_c[h * NN + i0 + row]           = cl;
            g_c[NH * NN + h * NN + i0 + row] = cr;
        }
    }
}

// ======= fused attention (VERIFIED R12 structure: warp = 2 rows x half-j) ===
#define TI 8

__global__ void __launch_bounds__(256)
attn_kernel(const float* __restrict__ a,
            const int* __restrict__ adj,
            const float* __restrict__ x_in_p,
            float* __restrict__ x_out_p,
            int mode) {                       // 0: layer0 (ELU), 1: layer1
    __shared__ float2 att_t[NN][TI];          // duplicated (p,p): 24576 B
    __shared__ float  red[8][TI][NF + 4];     // 17408 B
    __shared__ float2 grdup[TI][NF];          //  4096 B
    __shared__ float2 a4dup[NF];              //   512 B
    __shared__ float2 ms[TI][2];              //   128 B

    const float* x_in = mode ? g_x1 : x_in_p;
    float* x_out      = mode ? x_out_p : g_x1;

    int h   = blockIdx.y;
    int i0  = blockIdx.x * TI;
    int tid = threadIdx.x, lane = tid & 31, w = tid >> 5;
    int rp  = w >> 1;               // row pair: rows 2rp, 2rp+1
    int jh  = w & 1;                // j half: [jh*192, jh*192+192)

    // ---- stage duplicated operand tables ----
    for (int t = tid; t < TI * NF; t += 256) {
        int r = t >> 6, f = t & 63;
        float v = g_gr[(i0 + r) * DIM + h * NF + f];
        grdup[r][f] = make_float2(v, v);
    }
    if (tid < NF) { float v = 0.4f * a[tid]; a4dup[tid] = make_float2(v, v); }
    __syncthreads();

    // ---- phase 1: acc[i][jpair] += 0.4a[f] * |g_r[i,f] + g_l[j,f]| ----
    ull acc2[2][3];
#pragma unroll
    for (int il = 0; il < 2; il++)
#pragma unroll
        for (int jt = 0; jt < 3; jt++) acc2[il][jt] = 0ULL;

    const float* glT = g_glT + h * (NF * NN) + jh * 192 + 2 * lane;

#pragma unroll 1
    for (int fc = 0; fc < 16; fc++) {
        ull pa[4], pg0[4], pg1[4];
#pragma unroll
        for (int f4 = 0; f4 < 4; f4++) {
            pa[f4]  = *(const ull*)&a4dup[fc * 4 + f4];
            pg0[f4] = *(const ull*)&grdup[rp * 2][fc * 4 + f4];
            pg1[f4] = *(const ull*)&grdup[rp * 2 + 1][fc * 4 + f4];
        }
#pragma unroll
        for (int f4 = 0; f4 < 4; f4++) {
            const float* gp = glT + (fc * 4 + f4) * NN;
#pragma unroll
            for (int jt = 0; jt < 3; jt++) {
                ull gl2 = *(const ull*)(gp + jt * 64);
                acc2[0][jt] = fma2(pa[f4], abs2(add2(pg0[f4], gl2)), acc2[0][jt]);
                acc2[1][jt] = fma2(pa[f4], abs2(add2(pg1[f4], gl2)), acc2[1][jt]);
            }
        }
    }

    // ---- split-j masked softmax: local (m,s), then cross-half combine ----
    const float* clv = g_c + h * NN;
    const float* crv = g_c + NH * NN + h * NN;
    float p[2][6], mh[2];
#pragma unroll
    for (int il = 0; il < 2; il++) {
        int row = rp * 2 + il;
        int i = i0 + row;
        float cr6 = 0.6f * crv[i];
        unsigned vm = 0;
        float m = -1e30f;
#pragma unroll
        for (int jt = 0; jt < 3; jt++) {
            int j0 = jh * 192 + jt * 64 + 2 * lane;
            float2 gcl = *(const float2*)(clv + j0);
            int2   adv = *(const int2*)(adj + i * NN + j0);
            float u0, u1; unpack2(acc2[il][jt], u0, u1);
            float e0 = cr6 + fmaf(0.6f, gcl.x, u0);
            float e1 = cr6 + fmaf(0.6f, gcl.y, u1);
            p[il][jt * 2] = e0; p[il][jt * 2 + 1] = e1;
            if (adv.x || (j0 == i))     { vm |= 1u << (jt * 2);     m = fmaxf(m, e0); }
            if (adv.y || (j0 + 1 == i)) { vm |= 1u << (jt * 2 + 1); m = fmaxf(m, e1); }
        }
#pragma unroll
        for (int o = 16; o; o >>= 1) m = fmaxf(m, __shfl_xor_sync(0xffffffffu, m, o));
        float s = 0.f;
#pragma unroll
        for (int q = 0; q < 6; q++) {
            float pv = ((vm >> q) & 1) ? __expf(p[il][q] - m) : 0.f;
            p[il][q] = pv; s += pv;
        }
#pragma unroll
        for (int o = 16; o; o >>= 1) s += __shfl_xor_sync(0xffffffffu, s, o);
        mh[il] = m;
        if (lane == 0) ms[row][jh] = make_float2(m, s);
    }
    __syncthreads();

#pragma unroll
    for (int il = 0; il < 2; il++) {
        int row = rp * 2 + il;
        float2 v0 = ms[row][0], v1 = ms[row][1];
        float M = fmaxf(v0.x, v1.x);
        float S = v0.y * __expf(v0.x - M) + v1.y * __expf(v1.x - M);
        float scale = __expf(mh[il] - M) / S;
#pragma unroll
        for (int jt = 0; jt < 3; jt++) {
            int j0 = jh * 192 + jt * 64 + 2 * lane;
            float p0 = p[il][jt * 2] * scale;
            float p1 = p[il][jt * 2 + 1] * scale;
            att_t[j0][row]     = make_float2(p0, p0);
            att_t[j0 + 1][row] = make_float2(p1, p1);
        }
    }
    __syncthreads();

    // ---- phase 2: warp owns 48 j, accumulates all 8 rows for its f-pair ----
    ull o[TI];
#pragma unroll
    for (int q = 0; q < TI; q++) o[q] = 0ULL;

    const float* grp = g_gr + h * NF + 2 * lane;
    int jstart = w * 48;
#pragma unroll 4
    for (int jj = 0; jj < 48; jj++) {
        int j = jstart + jj;
        ull gp = *(const ull*)(grp + j * DIM);
#pragma unroll
        for (int q = 0; q < TI; q++)
            o[q] = fma2(*(const ull*)&att_t[j][q], gp, o[q]);
    }
#pragma unroll
    for (int q = 0; q < TI; q++)
        *(ull*)&red[w][q][2 * lane] = o[q];
    __syncthreads();

    // ---- reduce partials + activation + residual ----
    if (tid < 128) {
        int r = tid >> 4, f4 = (tid & 15) * 4;
        float4 s0 = *(const float4*)&red[0][r][f4];
        float4 s1 = *(const float4*)&red[1][r][f4];
        float4 s2 = *(const float4*)&red[2][r][f4];
        float4 s3 = *(const float4*)&red[3][r][f4];
        float4 s4 = *(const float4*)&red[4][r][f4];
        float4 s5 = *(const float4*)&red[5][r][f4];
        float4 s6 = *(const float4*)&red[6][r][f4];
        float4 s7 = *(const float4*)&red[7][r][f4];
        float r0 = ((s0.x + s1.x) + (s2.x + s3.x)) + ((s4.x + s5.x) + (s6.x + s7.x));
        float r1 = ((s0.y + s1.y) + (s2.y + s3.y)) + ((s4.y + s5.y) + (s6.y + s7.y));
        float r2 = ((s0.z + s1.z) + (s2.z + s3.z)) + ((s4.z + s5.z) + (s6.z + s7.z));
        float r3 = ((s0.w + s1.w) + (s2.w + s3.w)) + ((s4.w + s5.w) + (s6.w + s7.w));
        if (mode == 0) {       // ELU (alpha=1)
            r0 = r0 > 0.f ? r0 : expm1f(r0);
            r1 = r1 > 0.f ? r1 : expm1f(r1);
            r2 = r2 > 0.f ? r2 : expm1f(r2);
            r3 = r3 > 0.f ? r3 : expm1f(r3);
        }
        int gi = i0 + r;
        float4 xi = *(const float4*)&x_in[gi * DIM + h * NF + f4];
        *(float4*)&x_out[gi * DIM + h * NF + f4] =
            make_float4(xi.x + r0, xi.y + r1, xi.z + r2, xi.w + r3);
    }
}

// ---------------------------------------------------------------------------
extern "C" void kernel_launch(void* const* d_in, const int* in_sizes, int n_in,
                              void* d_out, int out_size) {
    const float* x   = (const float*)d_in[0];
    const int*   adj = (const int*)  d_in[1];
    const float* Wl0 = (const float*)d_in[2];
    const float* Wr0 = (const float*)d_in[3];
    const float* a0  = (const float*)d_in[4];
    const float* Wl1 = (const float*)d_in[5];
    const float* Wr1 = (const float*)d_in[6];
    const float* a1  = (const float*)d_in[7];
    float* out = (float*)d_out;

    dim3 gg(NH, NN / BM, KH);     // (8, 12, 4) = 384 blocks
    dim3 gr2(NN / RR, NH);        // (24, 8)
    dim3 ga(NN / TI, NH);         // (48, 8)    = 384 blocks

    // layer 0
    gemm_kernel<<<gg, 128>>>(x, Wl0, Wr0, 0);
    reduce_kernel<<<gr2, 256>>>(a0);
    attn_kernel<<<ga, 256>>>(a0, adj, x, out, 0);    // -> g_x1 (ELU + residual)
    // layer 1
    gemm_kernel<<<gg, 128>>>(x, Wl1, Wr1, 1);
    reduce_kernel<<<gr2, 256>>>(a1);
    attn_kernel<<<ga, 256>>>(a1, adj, x, out, 1);    // -> d_out (residual)
}